// round 1
// baseline (speedup 1.0000x reference)
#include <cuda_runtime.h>
#include <math.h>
#include <float.h>
#include <stdint.h>

#define N_NODES 4096
#define IN_DIM  1024
#define OUT_DIM 512
#define NHEADS  4
#define HDIM    128
#define TOPK    16
#define NEG_SLOPE 0.2f

// Scratch (no cudaMalloc allowed)
__device__ float g_Wh[N_NODES * OUT_DIM];     // 8 MB
__device__ float g_ssrc[N_NODES * NHEADS];
__device__ float g_sdst[N_NODES * NHEADS];
__device__ int   g_topk[N_NODES * TOPK];

// ---------------------------------------------------------------------------
// GEMM: Wh[m][n] = sum_k x[m][k] * W[n][k]   (M=4096, N=512, K=1024) fp32
// 64x64 block tile, K-tile 16, 256 threads, 4x4 per thread.
// ---------------------------------------------------------------------------
__global__ __launch_bounds__(256) void gemm_kernel(const float* __restrict__ x,
                                                   const float* __restrict__ W) {
    __shared__ float As[16][68];   // [k][m], padded: 68*4 bytes row stride (16B-aligned rows)
    __shared__ float Bs[16][68];   // [k][n]

    const int bm  = blockIdx.y << 6;
    const int bn  = blockIdx.x << 6;
    const int tid = threadIdx.x;

    const int lrow = tid >> 2;          // 0..63  (row within tile for loading)
    const int lk4  = (tid & 3) << 2;    // 0,4,8,12 (k sub-offset, float4)
    const int ty   = tid >> 4;          // 0..15 -> m group (4 rows)
    const int tx   = tid & 15;          // 0..15 -> n group (4 cols)

    const float* xg = x + (size_t)(bm + lrow) * IN_DIM + lk4;
    const float* wg = W + (size_t)(bn + lrow) * IN_DIM + lk4;

    float acc[4][4];
#pragma unroll
    for (int i = 0; i < 4; i++)
#pragma unroll
        for (int j = 0; j < 4; j++) acc[i][j] = 0.f;

    for (int k0 = 0; k0 < IN_DIM; k0 += 16) {
        float4 av = *reinterpret_cast<const float4*>(xg + k0);
        float4 bv = *reinterpret_cast<const float4*>(wg + k0);
        As[lk4 + 0][lrow] = av.x; As[lk4 + 1][lrow] = av.y;
        As[lk4 + 2][lrow] = av.z; As[lk4 + 3][lrow] = av.w;
        Bs[lk4 + 0][lrow] = bv.x; Bs[lk4 + 1][lrow] = bv.y;
        Bs[lk4 + 2][lrow] = bv.z; Bs[lk4 + 3][lrow] = bv.w;
        __syncthreads();
#pragma unroll
        for (int k = 0; k < 16; k++) {
            float4 a = *reinterpret_cast<const float4*>(&As[k][ty << 2]);
            float4 b = *reinterpret_cast<const float4*>(&Bs[k][tx << 2]);
            acc[0][0] += a.x * b.x; acc[0][1] += a.x * b.y; acc[0][2] += a.x * b.z; acc[0][3] += a.x * b.w;
            acc[1][0] += a.y * b.x; acc[1][1] += a.y * b.y; acc[1][2] += a.y * b.z; acc[1][3] += a.y * b.w;
            acc[2][0] += a.z * b.x; acc[2][1] += a.z * b.y; acc[2][2] += a.z * b.z; acc[2][3] += a.z * b.w;
            acc[3][0] += a.w * b.x; acc[3][1] += a.w * b.y; acc[3][2] += a.w * b.z; acc[3][3] += a.w * b.w;
        }
        __syncthreads();
    }

#pragma unroll
    for (int i = 0; i < 4; i++) {
        float4 v = make_float4(acc[i][0], acc[i][1], acc[i][2], acc[i][3]);
        *reinterpret_cast<float4*>(g_Wh + (size_t)(bm + (ty << 2) + i) * OUT_DIM + bn + (tx << 2)) = v;
    }
}

// ---------------------------------------------------------------------------
// Scores: s_src[n,h] = Wh[n,h,:].a[0:128], s_dst[n,h] = Wh[n,h,:].a[128:256]
// One warp per (n, head).
// ---------------------------------------------------------------------------
__global__ __launch_bounds__(128) void score_kernel(const float* __restrict__ a) {
    const int n    = blockIdx.x;
    const int h    = threadIdx.x >> 5;
    const int lane = threadIdx.x & 31;
    const float* row = g_Wh + (size_t)n * OUT_DIM + h * HDIM;
    float ss = 0.f, sd = 0.f;
#pragma unroll
    for (int i = lane; i < HDIM; i += 32) {
        float v = row[i];
        ss += v * a[i];
        sd += v * a[HDIM + i];
    }
#pragma unroll
    for (int o = 16; o; o >>= 1) {
        ss += __shfl_xor_sync(0xffffffffu, ss, o);
        sd += __shfl_xor_sync(0xffffffffu, sd, o);
    }
    if (lane == 0) {
        g_ssrc[n * NHEADS + h] = ss;
        g_sdst[n * NHEADS + h] = sd;
    }
}

// ---------------------------------------------------------------------------
// Top-16 per adj row. One warp per row. Tie-break: (value desc, index asc)
// — matches jax.lax.top_k stability.
// ---------------------------------------------------------------------------
__global__ __launch_bounds__(128) void topk_kernel(const float* __restrict__ adj) {
    const int row  = blockIdx.x * 4 + (threadIdx.x >> 5);
    const int lane = threadIdx.x & 31;
    const float* r = adj + (size_t)row * N_NODES;

    float vals[TOPK];
    int   idxs[TOPK];
#pragma unroll
    for (int i = 0; i < TOPK; i++) { vals[i] = -FLT_MAX; idxs[i] = 0x7fffffff; }

    // per-thread local top-16 over 128 strided (coalesced) elements
    for (int j = lane; j < N_NODES; j += 32) {
        float v = r[j];
        if (v > vals[TOPK - 1]) {            // strict >: equal value, later index loses
            int p = TOPK - 1;
            while (p > 0 && v > vals[p - 1]) {
                vals[p] = vals[p - 1];
                idxs[p] = idxs[p - 1];
                p--;
            }
            vals[p] = v;
            idxs[p] = j;
        }
    }

    // merge: 16 rounds of warp argmax over each thread's current list head
    int p = 0;
    for (int t = 0; t < TOPK; t++) {
        float bv = (p < TOPK) ? vals[p] : -FLT_MAX;
        int   bi = (p < TOPK) ? idxs[p] : 0x7fffffff;
#pragma unroll
        for (int o = 16; o; o >>= 1) {
            float ov = __shfl_xor_sync(0xffffffffu, bv, o);
            int   oi = __shfl_xor_sync(0xffffffffu, bi, o);
            if (ov > bv || (ov == bv && oi < bi)) { bv = ov; bi = oi; }
        }
        if (p < TOPK && idxs[p] == bi) p++;   // winner (indices unique) advances
        if (lane == 0) g_topk[row * TOPK + t] = bi;
    }
}

// ---------------------------------------------------------------------------
// Aggregate: per row i, softmax over 16 selected e[i,j,h], weighted sum of
// Wh rows, ELU. One block (128 threads) per row.
// ---------------------------------------------------------------------------
__global__ __launch_bounds__(128) void aggregate_kernel(float* __restrict__ out) {
    const int i   = blockIdx.x;
    const int tid = threadIdx.x;

    __shared__ int   sidx[TOPK];
    __shared__ float salpha[TOPK][NHEADS];

    if (tid < TOPK) sidx[tid] = g_topk[i * TOPK + tid];
    __syncthreads();

    if (tid < TOPK * NHEADS) {
        const int t = tid >> 2, h = tid & 3;
        float e = g_ssrc[i * NHEADS + h] + g_sdst[sidx[t] * NHEADS + h];
        e = (e >= 0.f) ? e : NEG_SLOPE * e;
        salpha[t][h] = e;
    }
    __syncthreads();

    if (tid < NHEADS) {
        const int h = tid;
        float m = -FLT_MAX;
#pragma unroll
        for (int t = 0; t < TOPK; t++) m = fmaxf(m, salpha[t][h]);
        float s = 0.f;
#pragma unroll
        for (int t = 0; t < TOPK; t++) {
            float ex = expf(salpha[t][h] - m);
            salpha[t][h] = ex;
            s += ex;
        }
        float inv = 1.f / s;
#pragma unroll
        for (int t = 0; t < TOPK; t++) salpha[t][h] *= inv;
    }
    __syncthreads();

    const int d = tid;   // 0..127
#pragma unroll
    for (int h = 0; h < NHEADS; h++) {
        float acc = 0.f;
#pragma unroll
        for (int t = 0; t < TOPK; t++)
            acc += salpha[t][h] * g_Wh[(size_t)sidx[t] * OUT_DIM + h * HDIM + d];
        out[(size_t)i * OUT_DIM + h * HDIM + d] = (acc > 0.f) ? acc : expm1f(acc);
    }
}

// ---------------------------------------------------------------------------
extern "C" void kernel_launch(void* const* d_in, const int* in_sizes, int n_in,
                              void* d_out, int out_size) {
    const float* x   = (const float*)d_in[0];
    const float* adj = (const float*)d_in[1];
    const float* W   = (const float*)d_in[2];
    const float* a   = (const float*)d_in[3];
    float* out = (float*)d_out;

    dim3 gg(OUT_DIM / 64, N_NODES / 64);
    gemm_kernel<<<gg, 256>>>(x, W);
    topk_kernel<<<N_NODES / 4, 128>>>(adj);
    score_kernel<<<N_NODES, 128>>>(a);
    aggregate_kernel<<<N_NODES, 128>>>(out);
}

// round 2
// speedup vs baseline: 3.5389x; 3.5389x over previous
#include <cuda_runtime.h>
#include <math.h>
#include <float.h>
#include <stdint.h>

#define N_NODES 4096
#define IN_DIM  1024
#define OUT_DIM 512
#define NHEADS  4
#define HDIM    128
#define TOPK    16
#define NEG_SLOPE 0.2f

#define BM 128
#define BN 128
#define BK 8

// Scratch (no cudaMalloc allowed)
__device__ float g_Wh[N_NODES * OUT_DIM];     // 8 MB
__device__ float g_ssrc[N_NODES * NHEADS];
__device__ float g_sdst[N_NODES * NHEADS];
__device__ int   g_topk[N_NODES * TOPK];

// packed dual-fp32 FMA: d.lo += a.lo*b.lo ; d.hi += a.hi*b.hi
__device__ __forceinline__ void fma2(unsigned long long& d,
                                     unsigned long long a,
                                     unsigned long long b) {
    asm("fma.rn.f32x2 %0, %1, %2, %0;" : "+l"(d) : "l"(a), "l"(b));
}

// ---------------------------------------------------------------------------
// GEMM: Wh[m][n] = sum_k x[m][k] * W[n][k]   (M=4096, N=512, K=1024) fp32
// 128x128 block tile, BK=8, 256 threads, 8x8 per thread via FFMA2.
// A is stored DUPLICATED in smem so ld.shared.v2.u64 yields (a,a) pairs.
// ---------------------------------------------------------------------------
__global__ __launch_bounds__(256) void gemm_kernel(const float* __restrict__ x,
                                                   const float* __restrict__ W) {
    __shared__ __align__(16) float AsD[2][BK][264];  // [k][2*m(+dup)], pad 264
    __shared__ __align__(16) float Bs [2][BK][136];  // [k][n], pad 136

    const int bm  = blockIdx.y * BM;
    const int bn  = blockIdx.x * BN;
    const int tid = threadIdx.x;

    const int lrow = tid >> 1;          // 0..127 (tile row for loading)
    const int lk   = (tid & 1) * 4;     // 0 or 4 (k sub-offset)

    const int ty = tid >> 4;            // 0..15 -> m group of 8
    const int tx = tid & 15;            // 0..15 -> n group of 8

    const float* xg = x + (size_t)(bm + lrow) * IN_DIM + lk;
    const float* wg = W + (size_t)(bn + lrow) * IN_DIM + lk;

    unsigned long long acc[8][4];
#pragma unroll
    for (int i = 0; i < 8; i++)
#pragma unroll
        for (int j = 0; j < 4; j++) acc[i][j] = 0ull;

    float4 av = *reinterpret_cast<const float4*>(xg);
    float4 bv = *reinterpret_cast<const float4*>(wg);

    // store tile 0 into buffer 0
    {
        ((float2*)AsD[0][lk + 0])[lrow] = make_float2(av.x, av.x);
        ((float2*)AsD[0][lk + 1])[lrow] = make_float2(av.y, av.y);
        ((float2*)AsD[0][lk + 2])[lrow] = make_float2(av.z, av.z);
        ((float2*)AsD[0][lk + 3])[lrow] = make_float2(av.w, av.w);
        Bs[0][lk + 0][lrow] = bv.x;
        Bs[0][lk + 1][lrow] = bv.y;
        Bs[0][lk + 2][lrow] = bv.z;
        Bs[0][lk + 3][lrow] = bv.w;
    }
    __syncthreads();

    int buf = 0;
    for (int k0 = BK; k0 <= IN_DIM; k0 += BK) {
        const bool more = (k0 < IN_DIM);
        if (more) {
            av = *reinterpret_cast<const float4*>(xg + k0);
            bv = *reinterpret_cast<const float4*>(wg + k0);
        }
#pragma unroll
        for (int k = 0; k < BK; k++) {
            // a dup pairs: 8 pairs = 4x 16B loads
            const ulonglong2* ap =
                reinterpret_cast<const ulonglong2*>(&AsD[buf][k][ty * 16]);
            const ulonglong2* bp =
                reinterpret_cast<const ulonglong2*>(&Bs[buf][k][tx * 8]);
            ulonglong2 a01 = ap[0], a23 = ap[1], a45 = ap[2], a67 = ap[3];
            ulonglong2 b03 = bp[0], b47 = bp[1];
            unsigned long long af[8] = {a01.x, a01.y, a23.x, a23.y,
                                        a45.x, a45.y, a67.x, a67.y};
            unsigned long long bf[4] = {b03.x, b03.y, b47.x, b47.y};
#pragma unroll
            for (int i = 0; i < 8; i++)
#pragma unroll
                for (int j = 0; j < 4; j++) fma2(acc[i][j], af[i], bf[j]);
        }
        if (more) {
            const int nb = buf ^ 1;
            ((float2*)AsD[nb][lk + 0])[lrow] = make_float2(av.x, av.x);
            ((float2*)AsD[nb][lk + 1])[lrow] = make_float2(av.y, av.y);
            ((float2*)AsD[nb][lk + 2])[lrow] = make_float2(av.z, av.z);
            ((float2*)AsD[nb][lk + 3])[lrow] = make_float2(av.w, av.w);
            Bs[nb][lk + 0][lrow] = bv.x;
            Bs[nb][lk + 1][lrow] = bv.y;
            Bs[nb][lk + 2][lrow] = bv.z;
            Bs[nb][lk + 3][lrow] = bv.w;
            __syncthreads();
            buf = nb;
        }
    }

#pragma unroll
    for (int i = 0; i < 8; i++) {
        float* orow = g_Wh + (size_t)(bm + ty * 8 + i) * OUT_DIM + bn + tx * 8;
#pragma unroll
        for (int j = 0; j < 4; j++)
            *reinterpret_cast<float2*>(orow + 2 * j) =
                *reinterpret_cast<float2*>(&acc[i][j]);
    }
}

// ---------------------------------------------------------------------------
// Scores: s_src[n,h] = Wh[n,h,:].a[0:128], s_dst[n,h] = Wh[n,h,:].a[128:256]
// One warp per (n, head).
// ---------------------------------------------------------------------------
__global__ __launch_bounds__(128) void score_kernel(const float* __restrict__ a) {
    const int n    = blockIdx.x;
    const int h    = threadIdx.x >> 5;
    const int lane = threadIdx.x & 31;
    const float4* row = reinterpret_cast<const float4*>(g_Wh + (size_t)n * OUT_DIM + h * HDIM);
    const float4* a0  = reinterpret_cast<const float4*>(a);
    const float4* a1  = reinterpret_cast<const float4*>(a + HDIM);
    float ss = 0.f, sd = 0.f;
    // HDIM/4 = 32 float4 per head: one per lane
    float4 v  = row[lane];
    float4 c0 = a0[lane];
    float4 c1 = a1[lane];
    ss = v.x * c0.x + v.y * c0.y + v.z * c0.z + v.w * c0.w;
    sd = v.x * c1.x + v.y * c1.y + v.z * c1.z + v.w * c1.w;
#pragma unroll
    for (int o = 16; o; o >>= 1) {
        ss += __shfl_xor_sync(0xffffffffu, ss, o);
        sd += __shfl_xor_sync(0xffffffffu, sd, o);
    }
    if (lane == 0) {
        g_ssrc[n * NHEADS + h] = ss;
        g_sdst[n * NHEADS + h] = sd;
    }
}

// ---------------------------------------------------------------------------
// Top-16 per adj row. One warp per row. Fully register-resident:
// predicated unrolled insertion (static indices) + static shift-down merge.
// Tie-break: (value desc, index asc) — matches jax.lax.top_k.
// ---------------------------------------------------------------------------
__device__ __forceinline__ void insert16(float (&vals)[TOPK], int (&idxs)[TOPK],
                                         float v, int j) {
    if (v > vals[TOPK - 1]) {
        float pv = FLT_MAX;
        int   pi = -1;
#pragma unroll
        for (int s = 0; s < TOPK; s++) {
            float cv = vals[s];
            int   ci = idxs[s];
            bool gp = v > pv;   // v belongs above slot s (shift)
            bool gc = v > cv;   // v belongs at slot s
            vals[s] = gp ? pv : (gc ? v : cv);
            idxs[s] = gp ? pi : (gc ? j : ci);
            pv = cv; pi = ci;
        }
    }
}

__global__ __launch_bounds__(128) void topk_kernel(const float* __restrict__ adj) {
    const int row  = blockIdx.x * 4 + (threadIdx.x >> 5);
    const int lane = threadIdx.x & 31;
    const float4* r4 = reinterpret_cast<const float4*>(adj + (size_t)row * N_NODES);

    float vals[TOPK];
    int   idxs[TOPK];
#pragma unroll
    for (int i = 0; i < TOPK; i++) { vals[i] = -FLT_MAX; idxs[i] = 0x7fffffff; }

    // per-thread local top-16 over 32 float4 (128 elements), coalesced
    for (int jj = lane; jj < N_NODES / 4; jj += 32) {
        float4 v = r4[jj];
        const int j0 = jj * 4;
        insert16(vals, idxs, v.x, j0 + 0);
        insert16(vals, idxs, v.y, j0 + 1);
        insert16(vals, idxs, v.z, j0 + 2);
        insert16(vals, idxs, v.w, j0 + 3);
    }

    // merge: 16 rounds of warp argmax over list heads; winner shifts down
#pragma unroll 1
    for (int t = 0; t < TOPK; t++) {
        float bv = vals[0];
        int   bi = idxs[0];
#pragma unroll
        for (int o = 16; o; o >>= 1) {
            float ov = __shfl_xor_sync(0xffffffffu, bv, o);
            int   oi = __shfl_xor_sync(0xffffffffu, bi, o);
            if (ov > bv || (ov == bv && oi < bi)) { bv = ov; bi = oi; }
        }
        const bool win = (idxs[0] == bi);   // indices unique across warp
        if (win) {
#pragma unroll
            for (int s = 0; s < TOPK - 1; s++) {
                vals[s] = vals[s + 1];
                idxs[s] = idxs[s + 1];
            }
            vals[TOPK - 1] = -FLT_MAX;
            idxs[TOPK - 1] = 0x7fffffff;
        }
        if (lane == 0) g_topk[row * TOPK + t] = bi;
    }
}

// ---------------------------------------------------------------------------
// Aggregate: per row i, softmax over 16 selected e[i,j,h], weighted sum of
// Wh rows, ELU. One block (128 threads) per row; float4 per thread, MLP=16.
// ---------------------------------------------------------------------------
__global__ __launch_bounds__(128) void aggregate_kernel(float* __restrict__ out) {
    const int i   = blockIdx.x;
    const int tid = threadIdx.x;

    __shared__ int   sidx[TOPK];
    __shared__ float salpha[TOPK][NHEADS];

    if (tid < TOPK) sidx[tid] = g_topk[i * TOPK + tid];
    __syncthreads();

    if (tid < TOPK * NHEADS) {
        const int t = tid >> 2, h = tid & 3;
        float e = g_ssrc[i * NHEADS + h] + g_sdst[sidx[t] * NHEADS + h];
        e = (e >= 0.f) ? e : NEG_SLOPE * e;
        salpha[t][h] = e;
    }
    __syncthreads();

    if (tid < NHEADS) {
        const int h = tid;
        float m = -FLT_MAX;
#pragma unroll
        for (int t = 0; t < TOPK; t++) m = fmaxf(m, salpha[t][h]);
        float s = 0.f;
#pragma unroll
        for (int t = 0; t < TOPK; t++) {
            float ex = expf(salpha[t][h] - m);
            salpha[t][h] = ex;
            s += ex;
        }
        float inv = 1.f / s;
#pragma unroll
        for (int t = 0; t < TOPK; t++) salpha[t][h] *= inv;
    }
    __syncthreads();

    // each thread owns one float4 chunk: f = tid (0..127), head = f >> 5
    const int f = tid;
    const int h = f >> 5;
    float4 acc = make_float4(0.f, 0.f, 0.f, 0.f);
#pragma unroll
    for (int t = 0; t < TOPK; t++) {
        const float4* p = reinterpret_cast<const float4*>(g_Wh + (size_t)sidx[t] * OUT_DIM);
        float4 w = p[f];
        float al = salpha[t][h];
        acc.x += al * w.x; acc.y += al * w.y;
        acc.z += al * w.z; acc.w += al * w.w;
    }
    float4 r;
    r.x = (acc.x > 0.f) ? acc.x : expm1f(acc.x);
    r.y = (acc.y > 0.f) ? acc.y : expm1f(acc.y);
    r.z = (acc.z > 0.f) ? acc.z : expm1f(acc.z);
    r.w = (acc.w > 0.f) ? acc.w : expm1f(acc.w);
    reinterpret_cast<float4*>(out + (size_t)i * OUT_DIM)[f] = r;
}

// ---------------------------------------------------------------------------
extern "C" void kernel_launch(void* const* d_in, const int* in_sizes, int n_in,
                              void* d_out, int out_size) {
    const float* x   = (const float*)d_in[0];
    const float* adj = (const float*)d_in[1];
    const float* W   = (const float*)d_in[2];
    const float* a   = (const float*)d_in[3];
    float* out = (float*)d_out;

    dim3 gg(OUT_DIM / BN, N_NODES / BM);
    gemm_kernel<<<gg, 256>>>(x, W);
    topk_kernel<<<N_NODES / 4, 128>>>(adj);
    score_kernel<<<N_NODES, 128>>>(a);
    aggregate_kernel<<<N_NODES, 128>>>(out);
}

// round 3
// speedup vs baseline: 4.8146x; 1.3605x over previous
#include <cuda_runtime.h>
#include <math.h>
#include <float.h>
#include <stdint.h>

#define N_NODES 4096
#define IN_DIM  1024
#define OUT_DIM 512
#define NHEADS  4
#define HDIM    128
#define TOPK    16
#define NEG_SLOPE 0.2f

#define BM 128
#define BN 128
#define BK 8

#define MAXC   512
#define THRESH 0.98f

// Scratch (no cudaMalloc allowed)
__device__ float g_Wh[N_NODES * OUT_DIM];     // 8 MB
__device__ float g_ssrc[N_NODES * NHEADS];
__device__ float g_sdst[N_NODES * NHEADS];
__device__ int   g_topk[N_NODES * TOPK];

// packed dual-fp32 FMA: d.lo += a.lo*b.lo ; d.hi += a.hi*b.hi
__device__ __forceinline__ void fma2(unsigned long long& d,
                                     unsigned long long a,
                                     unsigned long long b) {
    asm("fma.rn.f32x2 %0, %1, %2, %0;" : "+l"(d) : "l"(a), "l"(b));
}
// pack (s,s) into a 64-bit dual-fp32 register
__device__ __forceinline__ unsigned long long dup2(float s) {
    unsigned long long d;
    asm("mov.b64 %0, {%1, %1};" : "=l"(d) : "f"(s));
    return d;
}

// ---------------------------------------------------------------------------
// GEMM: Wh[m][n] = sum_k x[m][k] * W[n][k]   (M=4096, N=512, K=1024) fp32
// 128x128 tile, BK=8, 256 threads, 8x8 microtile via FFMA2.
// A read scalar from smem (dup'd in registers), B read as natural pairs.
// Per k-step/thread: 4x LDS.128 (64B) + 8 MOV64 + 32 FFMA2 (64 FMA).
// ---------------------------------------------------------------------------
__global__ __launch_bounds__(256) void gemm_kernel(const float* __restrict__ x,
                                                   const float* __restrict__ W) {
    __shared__ __align__(16) float As[2][BK][136];
    __shared__ __align__(16) float Bs[2][BK][136];

    const int bm  = blockIdx.y * BM;
    const int bn  = blockIdx.x * BN;
    const int tid = threadIdx.x;

    const int lrow = tid >> 1;          // 0..127 (tile row for loading)
    const int lk   = (tid & 1) * 4;     // 0 or 4 (k sub-offset)

    const int ty = tid >> 4;            // 0..15 -> m group of 8
    const int tx = tid & 15;            // 0..15 -> n group of 8

    const float* xg = x + (size_t)(bm + lrow) * IN_DIM + lk;
    const float* wg = W + (size_t)(bn + lrow) * IN_DIM + lk;

    unsigned long long acc[8][4];
#pragma unroll
    for (int i = 0; i < 8; i++)
#pragma unroll
        for (int j = 0; j < 4; j++) acc[i][j] = 0ull;

    float4 av = *reinterpret_cast<const float4*>(xg);
    float4 bv = *reinterpret_cast<const float4*>(wg);

    As[0][lk + 0][lrow] = av.x; As[0][lk + 1][lrow] = av.y;
    As[0][lk + 2][lrow] = av.z; As[0][lk + 3][lrow] = av.w;
    Bs[0][lk + 0][lrow] = bv.x; Bs[0][lk + 1][lrow] = bv.y;
    Bs[0][lk + 2][lrow] = bv.z; Bs[0][lk + 3][lrow] = bv.w;
    __syncthreads();

    int buf = 0;
    for (int k0 = BK; k0 <= IN_DIM; k0 += BK) {
        const bool more = (k0 < IN_DIM);
        if (more) {
            av = *reinterpret_cast<const float4*>(xg + k0);
            bv = *reinterpret_cast<const float4*>(wg + k0);
        }
#pragma unroll
        for (int k = 0; k < BK; k++) {
            const float4* ap = reinterpret_cast<const float4*>(&As[buf][k][ty * 8]);
            float4 a0 = ap[0], a1 = ap[1];
            const ulonglong2* bp =
                reinterpret_cast<const ulonglong2*>(&Bs[buf][k][tx * 8]);
            ulonglong2 b03 = bp[0], b47 = bp[1];
            unsigned long long af[8] = {dup2(a0.x), dup2(a0.y), dup2(a0.z), dup2(a0.w),
                                        dup2(a1.x), dup2(a1.y), dup2(a1.z), dup2(a1.w)};
            unsigned long long bf[4] = {b03.x, b03.y, b47.x, b47.y};
#pragma unroll
            for (int i = 0; i < 8; i++)
#pragma unroll
                for (int j = 0; j < 4; j++) fma2(acc[i][j], af[i], bf[j]);
        }
        if (more) {
            const int nb = buf ^ 1;
            As[nb][lk + 0][lrow] = av.x; As[nb][lk + 1][lrow] = av.y;
            As[nb][lk + 2][lrow] = av.z; As[nb][lk + 3][lrow] = av.w;
            Bs[nb][lk + 0][lrow] = bv.x; Bs[nb][lk + 1][lrow] = bv.y;
            Bs[nb][lk + 2][lrow] = bv.z; Bs[nb][lk + 3][lrow] = bv.w;
            __syncthreads();
            buf = nb;
        }
    }

#pragma unroll
    for (int i = 0; i < 8; i++) {
        float* orow = g_Wh + (size_t)(bm + ty * 8 + i) * OUT_DIM + bn + tx * 8;
#pragma unroll
        for (int j = 0; j < 4; j++)
            *reinterpret_cast<float2*>(orow + 2 * j) =
                *reinterpret_cast<float2*>(&acc[i][j]);
    }
}

// ---------------------------------------------------------------------------
// Scores: one warp per (n, head).
// ---------------------------------------------------------------------------
__global__ __launch_bounds__(128) void score_kernel(const float* __restrict__ a) {
    const int n    = blockIdx.x;
    const int h    = threadIdx.x >> 5;
    const int lane = threadIdx.x & 31;
    const float4* row = reinterpret_cast<const float4*>(g_Wh + (size_t)n * OUT_DIM + h * HDIM);
    const float4* a0  = reinterpret_cast<const float4*>(a);
    const float4* a1  = reinterpret_cast<const float4*>(a + HDIM);
    float4 v  = row[lane];
    float4 c0 = a0[lane];
    float4 c1 = a1[lane];
    float ss = v.x * c0.x + v.y * c0.y + v.z * c0.z + v.w * c0.w;
    float sd = v.x * c1.x + v.y * c1.y + v.z * c1.z + v.w * c1.w;
#pragma unroll
    for (int o = 16; o; o >>= 1) {
        ss += __shfl_xor_sync(0xffffffffu, ss, o);
        sd += __shfl_xor_sync(0xffffffffu, sd, o);
    }
    if (lane == 0) {
        g_ssrc[n * NHEADS + h] = ss;
        g_sdst[n * NHEADS + h] = sd;
    }
}

// ---------------------------------------------------------------------------
// Top-16. Lexicographic insertion (val desc, idx asc) so candidate order
// (atomic, nondeterministic) cannot change the result — matches jax.lax.top_k.
// ---------------------------------------------------------------------------
__device__ __forceinline__ void insert16(float (&vals)[TOPK], int (&idxs)[TOPK],
                                         float v, int j) {
    if (v > vals[TOPK - 1] || (v == vals[TOPK - 1] && j < idxs[TOPK - 1])) {
        float pv = FLT_MAX;
        int   pi = -1;
#pragma unroll
        for (int s = 0; s < TOPK; s++) {
            float cv = vals[s];
            int   ci = idxs[s];
            bool gp = (v > pv) || (v == pv && j < pi);   // belongs above slot s-1's old entry
            bool gc = (v > cv) || (v == cv && j < ci);   // belongs at slot s
            vals[s] = gp ? pv : (gc ? v : cv);
            idxs[s] = gp ? pi : (gc ? j : ci);
            pv = cv; pi = ci;
        }
    }
}

__global__ __launch_bounds__(128) void topk_kernel(const float* __restrict__ adj) {
    __shared__ int   scnt[4];
    __shared__ float scv[4][MAXC];
    __shared__ int   sci[4][MAXC];

    const int w    = threadIdx.x >> 5;
    const int lane = threadIdx.x & 31;
    const int row  = blockIdx.x * 4 + w;
    const float4* r4 = reinterpret_cast<const float4*>(adj + (size_t)row * N_NODES);

    if (lane == 0) scnt[w] = 0;
    __syncwarp();

    // Pass 1: collect candidates >= THRESH (rare -> cheap)
    for (int jj = lane; jj < N_NODES / 4; jj += 32) {
        float4 v = r4[jj];
        const int j0 = jj * 4;
        if (v.x >= THRESH) { int p = atomicAdd(&scnt[w], 1); if (p < MAXC) { scv[w][p] = v.x; sci[w][p] = j0 + 0; } }
        if (v.y >= THRESH) { int p = atomicAdd(&scnt[w], 1); if (p < MAXC) { scv[w][p] = v.y; sci[w][p] = j0 + 1; } }
        if (v.z >= THRESH) { int p = atomicAdd(&scnt[w], 1); if (p < MAXC) { scv[w][p] = v.z; sci[w][p] = j0 + 2; } }
        if (v.w >= THRESH) { int p = atomicAdd(&scnt[w], 1); if (p < MAXC) { scv[w][p] = v.w; sci[w][p] = j0 + 3; } }
    }
    __syncwarp();
    const int c = scnt[w];

    float vals[TOPK];
    int   idxs[TOPK];
#pragma unroll
    for (int i = 0; i < TOPK; i++) { vals[i] = -FLT_MAX; idxs[i] = 0x7fffffff; }

    if (c >= TOPK && c <= MAXC) {
        // fast path: top-16 among c candidates (c >= 16 => superset of top-16)
        for (int t = lane; t < c; t += 32)
            insert16(vals, idxs, scv[w][t], sci[w][t]);
    } else {
        // fallback: exact full scan (arbitrary data safety)
        for (int jj = lane; jj < N_NODES / 4; jj += 32) {
            float4 v = r4[jj];
            const int j0 = jj * 4;
            insert16(vals, idxs, v.x, j0 + 0);
            insert16(vals, idxs, v.y, j0 + 1);
            insert16(vals, idxs, v.z, j0 + 2);
            insert16(vals, idxs, v.w, j0 + 3);
        }
    }

    // merge: 16 rounds of warp argmax over list heads; winner shifts down
#pragma unroll 1
    for (int t = 0; t < TOPK; t++) {
        float bv = vals[0];
        int   bi = idxs[0];
#pragma unroll
        for (int o = 16; o; o >>= 1) {
            float ov = __shfl_xor_sync(0xffffffffu, bv, o);
            int   oi = __shfl_xor_sync(0xffffffffu, bi, o);
            if (ov > bv || (ov == bv && oi < bi)) { bv = ov; bi = oi; }
        }
        const bool win = (idxs[0] == bi) && (vals[0] == bv);
        if (win) {
#pragma unroll
            for (int s = 0; s < TOPK - 1; s++) {
                vals[s] = vals[s + 1];
                idxs[s] = idxs[s + 1];
            }
            vals[TOPK - 1] = -FLT_MAX;
            idxs[TOPK - 1] = 0x7fffffff;
        }
        if (lane == 0) g_topk[row * TOPK + t] = bi;
    }
}

// ---------------------------------------------------------------------------
// Aggregate: softmax over 16 neighbors, weighted Wh sum, ELU.
// One block (128 threads) per row; float4 per thread, MLP=16.
// ---------------------------------------------------------------------------
__global__ __launch_bounds__(128) void aggregate_kernel(float* __restrict__ out) {
    const int i   = blockIdx.x;
    const int tid = threadIdx.x;

    __shared__ int   sidx[TOPK];
    __shared__ float salpha[TOPK][NHEADS];

    if (tid < TOPK) sidx[tid] = g_topk[i * TOPK + tid];
    __syncthreads();

    if (tid < TOPK * NHEADS) {
        const int t = tid >> 2, h = tid & 3;
        float e = g_ssrc[i * NHEADS + h] + g_sdst[sidx[t] * NHEADS + h];
        e = (e >= 0.f) ? e : NEG_SLOPE * e;
        salpha[t][h] = e;
    }
    __syncthreads();

    if (tid < NHEADS) {
        const int h = tid;
        float m = -FLT_MAX;
#pragma unroll
        for (int t = 0; t < TOPK; t++) m = fmaxf(m, salpha[t][h]);
        float s = 0.f;
#pragma unroll
        for (int t = 0; t < TOPK; t++) {
            float ex = expf(salpha[t][h] - m);
            salpha[t][h] = ex;
            s += ex;
        }
        float inv = 1.f / s;
#pragma unroll
        for (int t = 0; t < TOPK; t++) salpha[t][h] *= inv;
    }
    __syncthreads();

    const int f = tid;          // float4 chunk 0..127
    const int h = f >> 5;       // head
    float4 acc = make_float4(0.f, 0.f, 0.f, 0.f);
#pragma unroll
    for (int t = 0; t < TOPK; t++) {
        const float4* p = reinterpret_cast<const float4*>(g_Wh + (size_t)sidx[t] * OUT_DIM);
        float4 wv = p[f];
        float al = salpha[t][h];
        acc.x += al * wv.x; acc.y += al * wv.y;
        acc.z += al * wv.z; acc.w += al * wv.w;
    }
    float4 r;
    r.x = (acc.x > 0.f) ? acc.x : expm1f(acc.x);
    r.y = (acc.y > 0.f) ? acc.y : expm1f(acc.y);
    r.z = (acc.z > 0.f) ? acc.z : expm1f(acc.z);
    r.w = (acc.w > 0.f) ? acc.w : expm1f(acc.w);
    reinterpret_cast<float4*>(out + (size_t)i * OUT_DIM)[f] = r;
}

// ---------------------------------------------------------------------------
extern "C" void kernel_launch(void* const* d_in, const int* in_sizes, int n_in,
                              void* d_out, int out_size) {
    const float* x   = (const float*)d_in[0];
    const float* adj = (const float*)d_in[1];
    const float* W   = (const float*)d_in[2];
    const float* a   = (const float*)d_in[3];
    float* out = (float*)d_out;

    dim3 gg(OUT_DIM / BN, N_NODES / BM);
    gemm_kernel<<<gg, 256>>>(x, W);
    topk_kernel<<<N_NODES / 4, 128>>>(adj);
    score_kernel<<<N_NODES, 128>>>(a);
    aggregate_kernel<<<N_NODES, 128>>>(out);
}

// round 5
// speedup vs baseline: 6.8908x; 1.4312x over previous
#include <cuda_runtime.h>
#include <cuda_bf16.h>
#include <math.h>
#include <float.h>
#include <stdint.h>

#define N_NODES 4096
#define IN_DIM  1024
#define OUT_DIM 512
#define NHEADS  4
#define HDIM    128
#define TOPK    16
#define NEG_SLOPE 0.2f

#define MAXC   512
#define THRESH 0.98f

#define KC  64          // bf16 per k-chunk (128 B row)
#define NIT 48          // 3072 effective K / 64
#define SMEM_DYN (65536 + 1024)

// Scratch (no cudaMalloc allowed)
__device__ float g_Wh[N_NODES * OUT_DIM];                 // 8 MB
__device__ __nv_bfloat16 g_Abf[(size_t)N_NODES * 2048];   // [x_hi | x_lo]  16 MB
__device__ __nv_bfloat16 g_Bbf[(size_t)OUT_DIM * 2048];   // [W_hi | W_lo]   2 MB
__device__ float g_ssrc[N_NODES * NHEADS];
__device__ float g_sdst[N_NODES * NHEADS];
__device__ int   g_topk[N_NODES * TOPK];

// ---------------------------------------------------------------------------
// helpers
// ---------------------------------------------------------------------------
__device__ __forceinline__ uint32_t smem_to_u32(const void* p) {
    uint32_t a;
    asm("{ .reg .u64 t; cvta.to.shared.u64 t, %1; cvt.u32.u64 %0, t; }"
        : "=r"(a) : "l"(p));
    return a;
}
__device__ __forceinline__ void ldsm4(uint32_t* r, uint32_t addr) {
    asm volatile("ldmatrix.sync.aligned.m8n8.x4.shared.b16 {%0,%1,%2,%3}, [%4];"
        : "=r"(r[0]), "=r"(r[1]), "=r"(r[2]), "=r"(r[3]) : "r"(addr));
}
__device__ __forceinline__ void mma16816(float* d, const uint32_t* a,
                                         uint32_t b0, uint32_t b1) {
    asm volatile("mma.sync.aligned.m16n8k16.row.col.f32.bf16.bf16.f32 "
        "{%0,%1,%2,%3}, {%4,%5,%6,%7}, {%8,%9}, {%0,%1,%2,%3};"
        : "+f"(d[0]), "+f"(d[1]), "+f"(d[2]), "+f"(d[3])
        : "r"(a[0]), "r"(a[1]), "r"(a[2]), "r"(a[3]), "r"(b0), "r"(b1));
}

// ---------------------------------------------------------------------------
// fp32 -> (hi, lo) bf16 split conversion
// ---------------------------------------------------------------------------
__device__ __forceinline__ void split4(float4 v, uint2& hi, uint2& lo) {
    __nv_bfloat16 hx = __float2bfloat16_rn(v.x), hy = __float2bfloat16_rn(v.y);
    __nv_bfloat16 hz = __float2bfloat16_rn(v.z), hw = __float2bfloat16_rn(v.w);
    float lx = v.x - __bfloat162float(hx), ly = v.y - __bfloat162float(hy);
    float lz = v.z - __bfloat162float(hz), lw = v.w - __bfloat162float(hw);
    __nv_bfloat162 h01 = __halves2bfloat162(hx, hy);
    __nv_bfloat162 h23 = __halves2bfloat162(hz, hw);
    __nv_bfloat162 l01 = __floats2bfloat162_rn(lx, ly);
    __nv_bfloat162 l23 = __floats2bfloat162_rn(lz, lw);
    hi.x = *reinterpret_cast<uint32_t*>(&h01); hi.y = *reinterpret_cast<uint32_t*>(&h23);
    lo.x = *reinterpret_cast<uint32_t*>(&l01); lo.y = *reinterpret_cast<uint32_t*>(&l23);
}

__global__ __launch_bounds__(256) void conv_x_kernel(const float* __restrict__ x) {
    int i = blockIdx.x * 256 + threadIdx.x;      // float4 index
    float4 v = reinterpret_cast<const float4*>(x)[i];
    int r = i >> 8, c4 = i & 255;
    uint2 hi, lo; split4(v, hi, lo);
    __nv_bfloat16* base = g_Abf + (size_t)r * 2048 + c4 * 4;
    *reinterpret_cast<uint2*>(base)        = hi;
    *reinterpret_cast<uint2*>(base + 1024) = lo;
}
__global__ __launch_bounds__(256) void conv_w_kernel(const float* __restrict__ W) {
    int i = blockIdx.x * 256 + threadIdx.x;
    float4 v = reinterpret_cast<const float4*>(W)[i];
    int r = i >> 8, c4 = i & 255;
    uint2 hi, lo; split4(v, hi, lo);
    __nv_bfloat16* base = g_Bbf + (size_t)r * 2048 + c4 * 4;
    *reinterpret_cast<uint2*>(base)        = hi;
    *reinterpret_cast<uint2*>(base + 1024) = lo;
}

// ---------------------------------------------------------------------------
// HMMA GEMM: Wh = x @ W^T via bf16x3 (hi*hi + lo*hi + hi*lo), fp32 accum.
// mma.sync m16n8k16, 128x128 CTA tile, 8 warps (warp tile 32m x 64n),
// double-buffered SW128 smem, ldmatrix operand loads.
// ---------------------------------------------------------------------------
__global__ __launch_bounds__(256, 1) void hmma_gemm_kernel() {
    extern __shared__ char smem_raw[];
    char* sm = (char*)(((uintptr_t)smem_raw + 1023) & ~(uintptr_t)1023);
    const uint32_t sb = smem_to_u32(sm);
    const int tid  = threadIdx.x;
    const int wid  = tid >> 5;
    const int lane = tid & 31;
    const int bm = blockIdx.y * 128;
    const int bn = blockIdx.x * 128;
    const int m0w = (wid & 3) * 32;   // warp m origin in tile
    const int n0w = (wid >> 2) * 64;  // warp n origin in tile

    // global loader mapping: 256 threads cover 128 rows x 128 B, 4 x uint4 each
    const int row  = tid >> 1;
    const int half = tid & 1;
    const __nv_bfloat16* gA = g_Abf + (size_t)(bm + row) * 2048 + half * 32;
    const __nv_bfloat16* gB = g_Bbf + (size_t)(bn + row) * 2048 + half * 32;
    const uint32_t strow = (uint32_t)row * 128;
    const uint32_t stswz = ((uint32_t)row & 7) << 4;

    // ldmatrix per-lane constants (SW128 rows of exactly 128 B:
    // swizzled = row*128 + (colbytes ^ ((row&7)<<4)) )
    const uint32_t arow  = lane & 15;
    const uint32_t acolx = (lane & 16) ? 16u : 0u;
    const uint32_t aswz  = (arow & 7) << 4;
    const uint32_t brow  = (lane & 7) + ((lane & 16) >> 1);
    const uint32_t bcolx = (lane & 8) ? 16u : 0u;
    const uint32_t bswz  = (brow & 7) << 4;

    float acc[2][8][4] = {};

    // prologue: tile 0 into buffer 0
    uint4 pa[4], pb[4];
#pragma unroll
    for (int i = 0; i < 4; i++) {
        pa[i] = reinterpret_cast<const uint4*>(gA)[i];
        pb[i] = reinterpret_cast<const uint4*>(gB)[i];
    }
#pragma unroll
    for (int i = 0; i < 4; i++) {
        uint32_t so = strow + (((uint32_t)(half * 64 + i * 16)) ^ stswz);
        *reinterpret_cast<uint4*>(sm + so)         = pa[i];
        *reinterpret_cast<uint4*>(sm + 32768 + so) = pb[i];
    }
    __syncthreads();

#pragma unroll 1
    for (int it = 0; it < NIT; it++) {
        const int buf = it & 1;
        const bool pre = (it + 1) < NIT;
        if (pre) {
            const int nit = it + 1;
            const int ak = (nit < 32) ? nit * KC : (nit - 32) * KC;
            const int bk = (nit < 16) ? nit * KC
                         : ((nit < 32) ? (nit - 16) * KC : 1024 + (nit - 32) * KC);
            const uint4* qa = reinterpret_cast<const uint4*>(gA + ak);
            const uint4* qb = reinterpret_cast<const uint4*>(gB + bk);
#pragma unroll
            for (int i = 0; i < 4; i++) { pa[i] = qa[i]; pb[i] = qb[i]; }
        }

        const uint32_t Ab = sb + buf * 16384;
        const uint32_t Bb = sb + 32768 + buf * 16384;
#pragma unroll
        for (int ks = 0; ks < 4; ks++) {
            uint32_t afr[2][4];
#pragma unroll
            for (int mf = 0; mf < 2; mf++)
                ldsm4(afr[mf],
                      Ab + (m0w + mf * 16 + arow) * 128 + ((ks * 32 + acolx) ^ aswz));
            uint32_t bfr[4][4];
#pragma unroll
            for (int nq = 0; nq < 4; nq++)
                ldsm4(bfr[nq],
                      Bb + (n0w + nq * 16 + brow) * 128 + ((ks * 32 + bcolx) ^ bswz));
#pragma unroll
            for (int mf = 0; mf < 2; mf++)
#pragma unroll
                for (int nf = 0; nf < 8; nf++)
                    mma16816(acc[mf][nf], afr[mf],
                             bfr[nf >> 1][(nf & 1) * 2], bfr[nf >> 1][(nf & 1) * 2 + 1]);
        }

        if (pre) {
            const int nb = buf ^ 1;
#pragma unroll
            for (int i = 0; i < 4; i++) {
                uint32_t so = strow + (((uint32_t)(half * 64 + i * 16)) ^ stswz);
                *reinterpret_cast<uint4*>(sm + nb * 16384 + so)         = pa[i];
                *reinterpret_cast<uint4*>(sm + 32768 + nb * 16384 + so) = pb[i];
            }
            __syncthreads();
        }
    }

    // epilogue: registers -> g_Wh
#pragma unroll
    for (int mf = 0; mf < 2; mf++) {
        const int r0 = bm + m0w + mf * 16 + (lane >> 2);
#pragma unroll
        for (int nf = 0; nf < 8; nf++) {
            const int c = bn + n0w + nf * 8 + (lane & 3) * 2;
            *reinterpret_cast<float2*>(g_Wh + (size_t)r0 * OUT_DIM + c) =
                make_float2(acc[mf][nf][0], acc[mf][nf][1]);
            *reinterpret_cast<float2*>(g_Wh + (size_t)(r0 + 8) * OUT_DIM + c) =
                make_float2(acc[mf][nf][2], acc[mf][nf][3]);
        }
    }
}

// ---------------------------------------------------------------------------
// Scores: one warp per (n, head).
// ---------------------------------------------------------------------------
__global__ __launch_bounds__(128) void score_kernel(const float* __restrict__ a) {
    const int n    = blockIdx.x;
    const int h    = threadIdx.x >> 5;
    const int lane = threadIdx.x & 31;
    const float4* row = reinterpret_cast<const float4*>(g_Wh + (size_t)n * OUT_DIM + h * HDIM);
    const float4* a0  = reinterpret_cast<const float4*>(a);
    const float4* a1  = reinterpret_cast<const float4*>(a + HDIM);
    float4 v  = row[lane];
    float4 c0 = a0[lane];
    float4 c1 = a1[lane];
    float ss = v.x * c0.x + v.y * c0.y + v.z * c0.z + v.w * c0.w;
    float sd = v.x * c1.x + v.y * c1.y + v.z * c1.z + v.w * c1.w;
#pragma unroll
    for (int o = 16; o; o >>= 1) {
        ss += __shfl_xor_sync(0xffffffffu, ss, o);
        sd += __shfl_xor_sync(0xffffffffu, sd, o);
    }
    if (lane == 0) {
        g_ssrc[n * NHEADS + h] = ss;
        g_sdst[n * NHEADS + h] = sd;
    }
}

// ---------------------------------------------------------------------------
// Top-16. Lexicographic insertion (val desc, idx asc) — matches jax.lax.top_k.
// ---------------------------------------------------------------------------
__device__ __forceinline__ void insert16(float (&vals)[TOPK], int (&idxs)[TOPK],
                                         float v, int j) {
    if (v > vals[TOPK - 1] || (v == vals[TOPK - 1] && j < idxs[TOPK - 1])) {
        float pv = FLT_MAX;
        int   pi = -1;
#pragma unroll
        for (int s = 0; s < TOPK; s++) {
            float cv = vals[s];
            int   ci = idxs[s];
            bool gp = (v > pv) || (v == pv && j < pi);
            bool gc = (v > cv) || (v == cv && j < ci);
            vals[s] = gp ? pv : (gc ? v : cv);
            idxs[s] = gp ? pi : (gc ? j : ci);
            pv = cv; pi = ci;
        }
    }
}

__global__ __launch_bounds__(128) void topk_kernel(const float* __restrict__ adj) {
    __shared__ int   scnt[4];
    __shared__ float scv[4][MAXC];
    __shared__ int   sci[4][MAXC];

    const int w    = threadIdx.x >> 5;
    const int lane = threadIdx.x & 31;
    const int row  = blockIdx.x * 4 + w;
    const float4* r4 = reinterpret_cast<const float4*>(adj + (size_t)row * N_NODES);

    if (lane == 0) scnt[w] = 0;
    __syncwarp();

    for (int jj = lane; jj < N_NODES / 4; jj += 32) {
        float4 v = r4[jj];
        const int j0 = jj * 4;
        if (v.x >= THRESH) { int p = atomicAdd(&scnt[w], 1); if (p < MAXC) { scv[w][p] = v.x; sci[w][p] = j0 + 0; } }
        if (v.y >= THRESH) { int p = atomicAdd(&scnt[w], 1); if (p < MAXC) { scv[w][p] = v.y; sci[w][p] = j0 + 1; } }
        if (v.z >= THRESH) { int p = atomicAdd(&scnt[w], 1); if (p < MAXC) { scv[w][p] = v.z; sci[w][p] = j0 + 2; } }
        if (v.w >= THRESH) { int p = atomicAdd(&scnt[w], 1); if (p < MAXC) { scv[w][p] = v.w; sci[w][p] = j0 + 3; } }
    }
    __syncwarp();
    const int c = scnt[w];

    float vals[TOPK];
    int   idxs[TOPK];
#pragma unroll
    for (int i = 0; i < TOPK; i++) { vals[i] = -FLT_MAX; idxs[i] = 0x7fffffff; }

    if (c >= TOPK && c <= MAXC) {
        for (int t = lane; t < c; t += 32)
            insert16(vals, idxs, scv[w][t], sci[w][t]);
    } else {
        for (int jj = lane; jj < N_NODES / 4; jj += 32) {
            float4 v = r4[jj];
            const int j0 = jj * 4;
            insert16(vals, idxs, v.x, j0 + 0);
            insert16(vals, idxs, v.y, j0 + 1);
            insert16(vals, idxs, v.z, j0 + 2);
            insert16(vals, idxs, v.w, j0 + 3);
        }
    }

#pragma unroll 1
    for (int t = 0; t < TOPK; t++) {
        float bv = vals[0];
        int   bi = idxs[0];
#pragma unroll
        for (int o = 16; o; o >>= 1) {
            float ov = __shfl_xor_sync(0xffffffffu, bv, o);
            int   oi = __shfl_xor_sync(0xffffffffu, bi, o);
            if (ov > bv || (ov == bv && oi < bi)) { bv = ov; bi = oi; }
        }
        const bool win = (idxs[0] == bi) && (vals[0] == bv);
        if (win) {
#pragma unroll
            for (int s = 0; s < TOPK - 1; s++) {
                vals[s] = vals[s + 1];
                idxs[s] = idxs[s + 1];
            }
            vals[TOPK - 1] = -FLT_MAX;
            idxs[TOPK - 1] = 0x7fffffff;
        }
        if (lane == 0) g_topk[row * TOPK + t] = bi;
    }
}

// ---------------------------------------------------------------------------
// Aggregate: softmax over 16 neighbors, weighted Wh sum, ELU.
// ---------------------------------------------------------------------------
__global__ __launch_bounds__(128) void aggregate_kernel(float* __restrict__ out) {
    const int i   = blockIdx.x;
    const int tid = threadIdx.x;

    __shared__ int   sidx[TOPK];
    __shared__ float salpha[TOPK][NHEADS];

    if (tid < TOPK) sidx[tid] = g_topk[i * TOPK + tid];
    __syncthreads();

    if (tid < TOPK * NHEADS) {
        const int t = tid >> 2, h = tid & 3;
        float e = g_ssrc[i * NHEADS + h] + g_sdst[sidx[t] * NHEADS + h];
        e = (e >= 0.f) ? e : NEG_SLOPE * e;
        salpha[t][h] = e;
    }
    __syncthreads();

    if (tid < NHEADS) {
        const int h = tid;
        float m = -FLT_MAX;
#pragma unroll
        for (int t = 0; t < TOPK; t++) m = fmaxf(m, salpha[t][h]);
        float s = 0.f;
#pragma unroll
        for (int t = 0; t < TOPK; t++) {
            float ex = expf(salpha[t][h] - m);
            salpha[t][h] = ex;
            s += ex;
        }
        float inv = 1.f / s;
#pragma unroll
        for (int t = 0; t < TOPK; t++) salpha[t][h] *= inv;
    }
    __syncthreads();

    const int f = tid;
    const int h = f >> 5;
    float4 acc = make_float4(0.f, 0.f, 0.f, 0.f);
#pragma unroll
    for (int t = 0; t < TOPK; t++) {
        const float4* p = reinterpret_cast<const float4*>(g_Wh + (size_t)sidx[t] * OUT_DIM);
        float4 wv = p[f];
        float al = salpha[t][h];
        acc.x += al * wv.x; acc.y += al * wv.y;
        acc.z += al * wv.z; acc.w += al * wv.w;
    }
    float4 r;
    r.x = (acc.x > 0.f) ? acc.x : expm1f(acc.x);
    r.y = (acc.y > 0.f) ? acc.y : expm1f(acc.y);
    r.z = (acc.z > 0.f) ? acc.z : expm1f(acc.z);
    r.w = (acc.w > 0.f) ? acc.w : expm1f(acc.w);
    reinterpret_cast<float4*>(out + (size_t)i * OUT_DIM)[f] = r;
}

// ---------------------------------------------------------------------------
extern "C" void kernel_launch(void* const* d_in, const int* in_sizes, int n_in,
                              void* d_out, int out_size) {
    const float* x   = (const float*)d_in[0];
    const float* adj = (const float*)d_in[1];
    const float* W   = (const float*)d_in[2];
    const float* a   = (const float*)d_in[3];
    float* out = (float*)d_out;

    cudaFuncSetAttribute(hmma_gemm_kernel,
                         cudaFuncAttributeMaxDynamicSharedMemorySize, SMEM_DYN);

    conv_x_kernel<<<4096, 256>>>(x);
    conv_w_kernel<<<512, 256>>>(W);
    hmma_gemm_kernel<<<dim3(OUT_DIM / 128, N_NODES / 128), 256, SMEM_DYN>>>();
    topk_kernel<<<N_NODES / 4, 128>>>(adj);
    score_kernel<<<N_NODES, 128>>>(a);
    aggregate_kernel<<<N_NODES, 128>>>(out);
}

// round 6
// speedup vs baseline: 7.0824x; 1.0278x over previous
#include <cuda_runtime.h>
#include <cuda_bf16.h>
#include <math.h>
#include <float.h>
#include <stdint.h>

#define N_NODES 4096
#define IN_DIM  1024
#define OUT_DIM 512
#define NHEADS  4
#define HDIM    128
#define TOPK    16
#define NEG_SLOPE 0.2f

#define MAXC   512
#define THRESH 0.98f

#define KC  64          // bf16 per k-chunk (128 B row)
#define NIT 48          // 3072 effective K / 64
#define SMEM_DYN (65536 + 1024)

// Scratch (no cudaMalloc allowed)
__device__ float g_Wh[N_NODES * OUT_DIM];                 // 8 MB
__device__ __nv_bfloat16 g_Abf[(size_t)N_NODES * 2048];   // [x_hi | x_lo]  16 MB
__device__ __nv_bfloat16 g_Bbf[(size_t)OUT_DIM * 2048];   // [W_hi | W_lo]   2 MB
__device__ float g_ssrc[N_NODES * NHEADS];
__device__ float g_sdst[N_NODES * NHEADS];
__device__ int   g_topk[N_NODES * TOPK];

// ---------------------------------------------------------------------------
// helpers
// ---------------------------------------------------------------------------
__device__ __forceinline__ uint32_t smem_to_u32(const void* p) {
    uint32_t a;
    asm("{ .reg .u64 t; cvta.to.shared.u64 t, %1; cvt.u32.u64 %0, t; }"
        : "=r"(a) : "l"(p));
    return a;
}
__device__ __forceinline__ void ldsm4(uint32_t* r, uint32_t addr) {
    asm volatile("ldmatrix.sync.aligned.m8n8.x4.shared.b16 {%0,%1,%2,%3}, [%4];"
        : "=r"(r[0]), "=r"(r[1]), "=r"(r[2]), "=r"(r[3]) : "r"(addr));
}
__device__ __forceinline__ void mma16816(float* d, const uint32_t* a,
                                         uint32_t b0, uint32_t b1) {
    asm volatile("mma.sync.aligned.m16n8k16.row.col.f32.bf16.bf16.f32 "
        "{%0,%1,%2,%3}, {%4,%5,%6,%7}, {%8,%9}, {%0,%1,%2,%3};"
        : "+f"(d[0]), "+f"(d[1]), "+f"(d[2]), "+f"(d[3])
        : "r"(a[0]), "r"(a[1]), "r"(a[2]), "r"(a[3]), "r"(b0), "r"(b1));
}

// ---------------------------------------------------------------------------
// fp32 -> (hi, lo) bf16 split conversion
// ---------------------------------------------------------------------------
__device__ __forceinline__ void split4(float4 v, uint2& hi, uint2& lo) {
    __nv_bfloat16 hx = __float2bfloat16_rn(v.x), hy = __float2bfloat16_rn(v.y);
    __nv_bfloat16 hz = __float2bfloat16_rn(v.z), hw = __float2bfloat16_rn(v.w);
    float lx = v.x - __bfloat162float(hx), ly = v.y - __bfloat162float(hy);
    float lz = v.z - __bfloat162float(hz), lw = v.w - __bfloat162float(hw);
    __nv_bfloat162 h01 = __halves2bfloat162(hx, hy);
    __nv_bfloat162 h23 = __halves2bfloat162(hz, hw);
    __nv_bfloat162 l01 = __floats2bfloat162_rn(lx, ly);
    __nv_bfloat162 l23 = __floats2bfloat162_rn(lz, lw);
    hi.x = *reinterpret_cast<uint32_t*>(&h01); hi.y = *reinterpret_cast<uint32_t*>(&h23);
    lo.x = *reinterpret_cast<uint32_t*>(&l01); lo.y = *reinterpret_cast<uint32_t*>(&l23);
}

__global__ __launch_bounds__(256) void conv_x_kernel(const float* __restrict__ x) {
    int i = blockIdx.x * 256 + threadIdx.x;      // float4 index
    float4 v = reinterpret_cast<const float4*>(x)[i];
    int r = i >> 8, c4 = i & 255;
    uint2 hi, lo; split4(v, hi, lo);
    __nv_bfloat16* base = g_Abf + (size_t)r * 2048 + c4 * 4;
    *reinterpret_cast<uint2*>(base)        = hi;
    *reinterpret_cast<uint2*>(base + 1024) = lo;
}
__global__ __launch_bounds__(256) void conv_w_kernel(const float* __restrict__ W) {
    int i = blockIdx.x * 256 + threadIdx.x;
    float4 v = reinterpret_cast<const float4*>(W)[i];
    int r = i >> 8, c4 = i & 255;
    uint2 hi, lo; split4(v, hi, lo);
    __nv_bfloat16* base = g_Bbf + (size_t)r * 2048 + c4 * 4;
    *reinterpret_cast<uint2*>(base)        = hi;
    *reinterpret_cast<uint2*>(base + 1024) = lo;
}

// ---------------------------------------------------------------------------
// HMMA GEMM: Wh = x @ W^T via bf16x3 (hi*hi + lo*hi + hi*lo), fp32 accum.
// mma.sync m16n8k16, 128x128 CTA tile, 8 warps (warp tile 32m x 64n),
// double-buffered SW128 smem, ldmatrix operand loads.
// ---------------------------------------------------------------------------
__global__ __launch_bounds__(256, 1) void hmma_gemm_kernel() {
    extern __shared__ char smem_raw[];
    char* sm = (char*)(((uintptr_t)smem_raw + 1023) & ~(uintptr_t)1023);
    const uint32_t sb = smem_to_u32(sm);
    const int tid  = threadIdx.x;
    const int wid  = tid >> 5;
    const int lane = tid & 31;
    const int bm = blockIdx.y * 128;
    const int bn = blockIdx.x * 128;
    const int m0w = (wid & 3) * 32;   // warp m origin in tile
    const int n0w = (wid >> 2) * 64;  // warp n origin in tile

    // global loader mapping: 256 threads cover 128 rows x 128 B, 4 x uint4 each
    const int row  = tid >> 1;
    const int half = tid & 1;
    const __nv_bfloat16* gA = g_Abf + (size_t)(bm + row) * 2048 + half * 32;
    const __nv_bfloat16* gB = g_Bbf + (size_t)(bn + row) * 2048 + half * 32;
    const uint32_t strow = (uint32_t)row * 128;
    const uint32_t stswz = ((uint32_t)row & 7) << 4;

    // ldmatrix per-lane constants (SW128 rows of exactly 128 B:
    // swizzled = row*128 + (colbytes ^ ((row&7)<<4)) )
    const uint32_t arow  = lane & 15;
    const uint32_t acolx = (lane & 16) ? 16u : 0u;
    const uint32_t aswz  = (arow & 7) << 4;
    const uint32_t brow  = (lane & 7) + ((lane & 16) >> 1);
    const uint32_t bcolx = (lane & 8) ? 16u : 0u;
    const uint32_t bswz  = (brow & 7) << 4;

    float acc[2][8][4] = {};

    // prologue: tile 0 into buffer 0
    uint4 pa[4], pb[4];
#pragma unroll
    for (int i = 0; i < 4; i++) {
        pa[i] = reinterpret_cast<const uint4*>(gA)[i];
        pb[i] = reinterpret_cast<const uint4*>(gB)[i];
    }
#pragma unroll
    for (int i = 0; i < 4; i++) {
        uint32_t so = strow + (((uint32_t)(half * 64 + i * 16)) ^ stswz);
        *reinterpret_cast<uint4*>(sm + so)         = pa[i];
        *reinterpret_cast<uint4*>(sm + 32768 + so) = pb[i];
    }
    __syncthreads();

#pragma unroll 1
    for (int it = 0; it < NIT; it++) {
        const int buf = it & 1;
        const bool pre = (it + 1) < NIT;
        if (pre) {
            const int nit = it + 1;
            const int ak = (nit < 32) ? nit * KC : (nit - 32) * KC;
            const int bk = (nit < 16) ? nit * KC
                         : ((nit < 32) ? (nit - 16) * KC : 1024 + (nit - 32) * KC);
            const uint4* qa = reinterpret_cast<const uint4*>(gA + ak);
            const uint4* qb = reinterpret_cast<const uint4*>(gB + bk);
#pragma unroll
            for (int i = 0; i < 4; i++) { pa[i] = qa[i]; pb[i] = qb[i]; }
        }

        const uint32_t Ab = sb + buf * 16384;
        const uint32_t Bb = sb + 32768 + buf * 16384;
#pragma unroll
        for (int ks = 0; ks < 4; ks++) {
            uint32_t afr[2][4];
#pragma unroll
            for (int mf = 0; mf < 2; mf++)
                ldsm4(afr[mf],
                      Ab + (m0w + mf * 16 + arow) * 128 + ((ks * 32 + acolx) ^ aswz));
            uint32_t bfr[4][4];
#pragma unroll
            for (int nq = 0; nq < 4; nq++)
                ldsm4(bfr[nq],
                      Bb + (n0w + nq * 16 + brow) * 128 + ((ks * 32 + bcolx) ^ bswz));
#pragma unroll
            for (int mf = 0; mf < 2; mf++)
#pragma unroll
                for (int nf = 0; nf < 8; nf++)
                    mma16816(acc[mf][nf], afr[mf],
                             bfr[nf >> 1][(nf & 1) * 2], bfr[nf >> 1][(nf & 1) * 2 + 1]);
        }

        if (pre) {
            const int nb = buf ^ 1;
#pragma unroll
            for (int i = 0; i < 4; i++) {
                uint32_t so = strow + (((uint32_t)(half * 64 + i * 16)) ^ stswz);
                *reinterpret_cast<uint4*>(sm + nb * 16384 + so)         = pa[i];
                *reinterpret_cast<uint4*>(sm + 32768 + nb * 16384 + so) = pb[i];
            }
            __syncthreads();
        }
    }

    // epilogue: registers -> g_Wh
#pragma unroll
    for (int mf = 0; mf < 2; mf++) {
        const int r0 = bm + m0w + mf * 16 + (lane >> 2);
#pragma unroll
        for (int nf = 0; nf < 8; nf++) {
            const int c = bn + n0w + nf * 8 + (lane & 3) * 2;
            *reinterpret_cast<float2*>(g_Wh + (size_t)r0 * OUT_DIM + c) =
                make_float2(acc[mf][nf][0], acc[mf][nf][1]);
            *reinterpret_cast<float2*>(g_Wh + (size_t)(r0 + 8) * OUT_DIM + c) =
                make_float2(acc[mf][nf][2], acc[mf][nf][3]);
        }
    }
}

// ---------------------------------------------------------------------------
// Scores: one warp per (n, head).
// ---------------------------------------------------------------------------
__global__ __launch_bounds__(128) void score_kernel(const float* __restrict__ a) {
    const int n    = blockIdx.x;
    const int h    = threadIdx.x >> 5;
    const int lane = threadIdx.x & 31;
    const float4* row = reinterpret_cast<const float4*>(g_Wh + (size_t)n * OUT_DIM + h * HDIM);
    const float4* a0  = reinterpret_cast<const float4*>(a);
    const float4* a1  = reinterpret_cast<const float4*>(a + HDIM);
    float4 v  = row[lane];
    float4 c0 = a0[lane];
    float4 c1 = a1[lane];
    float ss = v.x * c0.x + v.y * c0.y + v.z * c0.z + v.w * c0.w;
    float sd = v.x * c1.x + v.y * c1.y + v.z * c1.z + v.w * c1.w;
#pragma unroll
    for (int o = 16; o; o >>= 1) {
        ss += __shfl_xor_sync(0xffffffffu, ss, o);
        sd += __shfl_xor_sync(0xffffffffu, sd, o);
    }
    if (lane == 0) {
        g_ssrc[n * NHEADS + h] = ss;
        g_sdst[n * NHEADS + h] = sd;
    }
}

// ---------------------------------------------------------------------------
// Top-16. Lexicographic insertion (val desc, idx asc) — matches jax.lax.top_k.
// ---------------------------------------------------------------------------
__device__ __forceinline__ void insert16(float (&vals)[TOPK], int (&idxs)[TOPK],
                                         float v, int j) {
    if (v > vals[TOPK - 1] || (v == vals[TOPK - 1] && j < idxs[TOPK - 1])) {
        float pv = FLT_MAX;
        int   pi = -1;
#pragma unroll
        for (int s = 0; s < TOPK; s++) {
            float cv = vals[s];
            int   ci = idxs[s];
            bool gp = (v > pv) || (v == pv && j < pi);
            bool gc = (v > cv) || (v == cv && j < ci);
            vals[s] = gp ? pv : (gc ? v : cv);
            idxs[s] = gp ? pi : (gc ? j : ci);
            pv = cv; pi = ci;
        }
    }
}

__global__ __launch_bounds__(128) void topk_kernel(const float* __restrict__ adj) {
    __shared__ int   scnt[4];
    __shared__ float scv[4][MAXC];
    __shared__ int   sci[4][MAXC];

    const int w    = threadIdx.x >> 5;
    const int lane = threadIdx.x & 31;
    const int row  = blockIdx.x * 4 + w;
    const float4* r4 = reinterpret_cast<const float4*>(adj + (size_t)row * N_NODES);

    if (lane == 0) scnt[w] = 0;
    __syncwarp();

    // Pass 1: candidates >= THRESH. 4 independent LDG.128 per iteration
    // (MLP>=4) + one fmax-reduced threshold test per float4.
#pragma unroll 1
    for (int base = 0; base < N_NODES / 4; base += 128) {
        float4 v0 = r4[base + lane];
        float4 v1 = r4[base + lane + 32];
        float4 v2 = r4[base + lane + 64];
        float4 v3 = r4[base + lane + 96];
#pragma unroll
        for (int q = 0; q < 4; q++) {
            float4 v = (q == 0) ? v0 : (q == 1) ? v1 : (q == 2) ? v2 : v3;
            const int j0 = (base + lane + q * 32) * 4;
            float mx = fmaxf(fmaxf(v.x, v.y), fmaxf(v.z, v.w));
            if (mx >= THRESH) {
                if (v.x >= THRESH) { int p = atomicAdd(&scnt[w], 1); if (p < MAXC) { scv[w][p] = v.x; sci[w][p] = j0 + 0; } }
                if (v.y >= THRESH) { int p = atomicAdd(&scnt[w], 1); if (p < MAXC) { scv[w][p] = v.y; sci[w][p] = j0 + 1; } }
                if (v.z >= THRESH) { int p = atomicAdd(&scnt[w], 1); if (p < MAXC) { scv[w][p] = v.z; sci[w][p] = j0 + 2; } }
                if (v.w >= THRESH) { int p = atomicAdd(&scnt[w], 1); if (p < MAXC) { scv[w][p] = v.w; sci[w][p] = j0 + 3; } }
            }
        }
    }
    __syncwarp();
    const int c = scnt[w];

    float vals[TOPK];
    int   idxs[TOPK];
#pragma unroll
    for (int i = 0; i < TOPK; i++) { vals[i] = -FLT_MAX; idxs[i] = 0x7fffffff; }

    if (c >= TOPK && c <= MAXC) {
        for (int t = lane; t < c; t += 32)
            insert16(vals, idxs, scv[w][t], sci[w][t]);
    } else {
        // fallback: exact full scan (arbitrary data safety)
        for (int jj = lane; jj < N_NODES / 4; jj += 32) {
            float4 v = r4[jj];
            const int j0 = jj * 4;
            insert16(vals, idxs, v.x, j0 + 0);
            insert16(vals, idxs, v.y, j0 + 1);
            insert16(vals, idxs, v.z, j0 + 2);
            insert16(vals, idxs, v.w, j0 + 3);
        }
    }

#pragma unroll 1
    for (int t = 0; t < TOPK; t++) {
        float bv = vals[0];
        int   bi = idxs[0];
#pragma unroll
        for (int o = 16; o; o >>= 1) {
            float ov = __shfl_xor_sync(0xffffffffu, bv, o);
            int   oi = __shfl_xor_sync(0xffffffffu, bi, o);
            if (ov > bv || (ov == bv && oi < bi)) { bv = ov; bi = oi; }
        }
        const bool win = (idxs[0] == bi) && (vals[0] == bv);
        if (win) {
#pragma unroll
            for (int s = 0; s < TOPK - 1; s++) {
                vals[s] = vals[s + 1];
                idxs[s] = idxs[s + 1];
            }
            vals[TOPK - 1] = -FLT_MAX;
            idxs[TOPK - 1] = 0x7fffffff;
        }
        if (lane == 0) g_topk[row * TOPK + t] = bi;
    }
}

// ---------------------------------------------------------------------------
// Aggregate: softmax over 16 neighbors, weighted Wh sum, ELU.
// ---------------------------------------------------------------------------
__global__ __launch_bounds__(128) void aggregate_kernel(float* __restrict__ out) {
    const int i   = blockIdx.x;
    const int tid = threadIdx.x;

    __shared__ int   sidx[TOPK];
    __shared__ float salpha[TOPK][NHEADS];

    if (tid < TOPK) sidx[tid] = g_topk[i * TOPK + tid];
    __syncthreads();

    if (tid < TOPK * NHEADS) {
        const int t = tid >> 2, h = tid & 3;
        float e = g_ssrc[i * NHEADS + h] + g_sdst[sidx[t] * NHEADS + h];
        e = (e >= 0.f) ? e : NEG_SLOPE * e;
        salpha[t][h] = e;
    }
    __syncthreads();

    if (tid < NHEADS) {
        const int h = tid;
        float m = -FLT_MAX;
#pragma unroll
        for (int t = 0; t < TOPK; t++) m = fmaxf(m, salpha[t][h]);
        float s = 0.f;
#pragma unroll
        for (int t = 0; t < TOPK; t++) {
            float ex = expf(salpha[t][h] - m);
            salpha[t][h] = ex;
            s += ex;
        }
        float inv = 1.f / s;
#pragma unroll
        for (int t = 0; t < TOPK; t++) salpha[t][h] *= inv;
    }
    __syncthreads();

    const int f = tid;
    const int h = f >> 5;
    float4 acc = make_float4(0.f, 0.f, 0.f, 0.f);
#pragma unroll
    for (int t = 0; t < TOPK; t++) {
        const float4* p = reinterpret_cast<const float4*>(g_Wh + (size_t)sidx[t] * OUT_DIM);
        float4 wv = p[f];
        float al = salpha[t][h];
        acc.x += al * wv.x; acc.y += al * wv.y;
        acc.z += al * wv.z; acc.w += al * wv.w;
    }
    float4 r;
    r.x = (acc.x > 0.f) ? acc.x : expm1f(acc.x);
    r.y = (acc.y > 0.f) ? acc.y : expm1f(acc.y);
    r.z = (acc.z > 0.f) ? acc.z : expm1f(acc.z);
    r.w = (acc.w > 0.f) ? acc.w : expm1f(acc.w);
    reinterpret_cast<float4*>(out + (size_t)i * OUT_DIM)[f] = r;
}

// ---------------------------------------------------------------------------
extern "C" void kernel_launch(void* const* d_in, const int* in_sizes, int n_in,
                              void* d_out, int out_size) {
    const float* x   = (const float*)d_in[0];
    const float* adj = (const float*)d_in[1];
    const float* W   = (const float*)d_in[2];
    const float* a   = (const float*)d_in[3];
    float* out = (float*)d_out;

    cudaFuncSetAttribute(hmma_gemm_kernel,
                         cudaFuncAttributeMaxDynamicSharedMemorySize, SMEM_DYN);

    conv_x_kernel<<<4096, 256>>>(x);
    conv_w_kernel<<<512, 256>>>(W);
    hmma_gemm_kernel<<<dim3(OUT_DIM / 128, N_NODES / 128), 256, SMEM_DYN>>>();
    topk_kernel<<<N_NODES / 4, 128>>>(adj);
    score_kernel<<<N_NODES, 128>>>(a);
    aggregate_kernel<<<N_NODES, 128>>>(out);
}

// round 7
// speedup vs baseline: 7.4007x; 1.0449x over previous
#include <cuda_runtime.h>
#include <cuda_bf16.h>
#include <math.h>
#include <float.h>
#include <stdint.h>

#define N_NODES 4096
#define IN_DIM  1024
#define OUT_DIM 512
#define NHEADS  4
#define HDIM    128
#define TOPK    16
#define NEG_SLOPE 0.2f

#define MAXC   512
#define THRESH 0.98f

#define KC  64          // bf16 per k-chunk (128 B row)
#define NIT 48          // 3072 effective K / 64
#define SMEM_DYN (65536 + 1024)

// Scratch (no cudaMalloc allowed)
__device__ float g_Wh[N_NODES * OUT_DIM];                 // 8 MB
__device__ __nv_bfloat16 g_Abf[(size_t)N_NODES * 2048];   // [x_hi | x_lo]  16 MB
__device__ __nv_bfloat16 g_Bbf[(size_t)OUT_DIM * 2048];   // [W_hi | W_lo]   2 MB
__device__ float g_ssrc[N_NODES * NHEADS];
__device__ float g_sdst[N_NODES * NHEADS];
__device__ int   g_topk[N_NODES * TOPK];

// ---------------------------------------------------------------------------
// helpers
// ---------------------------------------------------------------------------
__device__ __forceinline__ uint32_t smem_to_u32(const void* p) {
    uint32_t a;
    asm("{ .reg .u64 t; cvta.to.shared.u64 t, %1; cvt.u32.u64 %0, t; }"
        : "=r"(a) : "l"(p));
    return a;
}
__device__ __forceinline__ void ldsm4(uint32_t* r, uint32_t addr) {
    asm volatile("ldmatrix.sync.aligned.m8n8.x4.shared.b16 {%0,%1,%2,%3}, [%4];"
        : "=r"(r[0]), "=r"(r[1]), "=r"(r[2]), "=r"(r[3]) : "r"(addr));
}
__device__ __forceinline__ void mma16816(float* d, const uint32_t* a,
                                         uint32_t b0, uint32_t b1) {
    asm volatile("mma.sync.aligned.m16n8k16.row.col.f32.bf16.bf16.f32 "
        "{%0,%1,%2,%3}, {%4,%5,%6,%7}, {%8,%9}, {%0,%1,%2,%3};"
        : "+f"(d[0]), "+f"(d[1]), "+f"(d[2]), "+f"(d[3])
        : "r"(a[0]), "r"(a[1]), "r"(a[2]), "r"(a[3]), "r"(b0), "r"(b1));
}

// ---------------------------------------------------------------------------
// fp32 -> (hi, lo) bf16 split conversion
// ---------------------------------------------------------------------------
__device__ __forceinline__ void split4(float4 v, uint2& hi, uint2& lo) {
    __nv_bfloat16 hx = __float2bfloat16_rn(v.x), hy = __float2bfloat16_rn(v.y);
    __nv_bfloat16 hz = __float2bfloat16_rn(v.z), hw = __float2bfloat16_rn(v.w);
    float lx = v.x - __bfloat162float(hx), ly = v.y - __bfloat162float(hy);
    float lz = v.z - __bfloat162float(hz), lw = v.w - __bfloat162float(hw);
    __nv_bfloat162 h01 = __halves2bfloat162(hx, hy);
    __nv_bfloat162 h23 = __halves2bfloat162(hz, hw);
    __nv_bfloat162 l01 = __floats2bfloat162_rn(lx, ly);
    __nv_bfloat162 l23 = __floats2bfloat162_rn(lz, lw);
    hi.x = *reinterpret_cast<uint32_t*>(&h01); hi.y = *reinterpret_cast<uint32_t*>(&h23);
    lo.x = *reinterpret_cast<uint32_t*>(&l01); lo.y = *reinterpret_cast<uint32_t*>(&l23);
}

__global__ __launch_bounds__(256) void conv_x_kernel(const float* __restrict__ x) {
    int i = blockIdx.x * 256 + threadIdx.x;      // float4 index
    float4 v = reinterpret_cast<const float4*>(x)[i];
    int r = i >> 8, c4 = i & 255;
    uint2 hi, lo; split4(v, hi, lo);
    __nv_bfloat16* base = g_Abf + (size_t)r * 2048 + c4 * 4;
    *reinterpret_cast<uint2*>(base)        = hi;
    *reinterpret_cast<uint2*>(base + 1024) = lo;
}
__global__ __launch_bounds__(256) void conv_w_kernel(const float* __restrict__ W) {
    int i = blockIdx.x * 256 + threadIdx.x;
    float4 v = reinterpret_cast<const float4*>(W)[i];
    int r = i >> 8, c4 = i & 255;
    uint2 hi, lo; split4(v, hi, lo);
    __nv_bfloat16* base = g_Bbf + (size_t)r * 2048 + c4 * 4;
    *reinterpret_cast<uint2*>(base)        = hi;
    *reinterpret_cast<uint2*>(base + 1024) = lo;
}

// ---------------------------------------------------------------------------
// HMMA GEMM: Wh = x @ W^T via bf16x3 (hi*hi + lo*hi + hi*lo), fp32 accum.
// mma.sync m16n8k16, 128x128 CTA tile, 8 warps (warp tile 32m x 64n),
// double-buffered SW128 smem, ldmatrix operand loads.
// ---------------------------------------------------------------------------
__global__ __launch_bounds__(256, 1) void hmma_gemm_kernel() {
    extern __shared__ char smem_raw[];
    char* sm = (char*)(((uintptr_t)smem_raw + 1023) & ~(uintptr_t)1023);
    const uint32_t sb = smem_to_u32(sm);
    const int tid  = threadIdx.x;
    const int wid  = tid >> 5;
    const int lane = tid & 31;
    const int bm = blockIdx.y * 128;
    const int bn = blockIdx.x * 128;
    const int m0w = (wid & 3) * 32;   // warp m origin in tile
    const int n0w = (wid >> 2) * 64;  // warp n origin in tile

    // global loader mapping: 256 threads cover 128 rows x 128 B, 4 x uint4 each
    const int row  = tid >> 1;
    const int half = tid & 1;
    const __nv_bfloat16* gA = g_Abf + (size_t)(bm + row) * 2048 + half * 32;
    const __nv_bfloat16* gB = g_Bbf + (size_t)(bn + row) * 2048 + half * 32;
    const uint32_t strow = (uint32_t)row * 128;
    const uint32_t stswz = ((uint32_t)row & 7) << 4;

    // ldmatrix per-lane constants (SW128 rows of exactly 128 B:
    // swizzled = row*128 + (colbytes ^ ((row&7)<<4)) )
    const uint32_t arow  = lane & 15;
    const uint32_t acolx = (lane & 16) ? 16u : 0u;
    const uint32_t aswz  = (arow & 7) << 4;
    const uint32_t brow  = (lane & 7) + ((lane & 16) >> 1);
    const uint32_t bcolx = (lane & 8) ? 16u : 0u;
    const uint32_t bswz  = (brow & 7) << 4;

    float acc[2][8][4] = {};

    // prologue: tile 0 into buffer 0
    uint4 pa[4], pb[4];
#pragma unroll
    for (int i = 0; i < 4; i++) {
        pa[i] = reinterpret_cast<const uint4*>(gA)[i];
        pb[i] = reinterpret_cast<const uint4*>(gB)[i];
    }
#pragma unroll
    for (int i = 0; i < 4; i++) {
        uint32_t so = strow + (((uint32_t)(half * 64 + i * 16)) ^ stswz);
        *reinterpret_cast<uint4*>(sm + so)         = pa[i];
        *reinterpret_cast<uint4*>(sm + 32768 + so) = pb[i];
    }
    __syncthreads();

#pragma unroll 1
    for (int it = 0; it < NIT; it++) {
        const int buf = it & 1;
        const bool pre = (it + 1) < NIT;
        if (pre) {
            const int nit = it + 1;
            const int ak = (nit < 32) ? nit * KC : (nit - 32) * KC;
            const int bk = (nit < 16) ? nit * KC
                         : ((nit < 32) ? (nit - 16) * KC : 1024 + (nit - 32) * KC);
            const uint4* qa = reinterpret_cast<const uint4*>(gA + ak);
            const uint4* qb = reinterpret_cast<const uint4*>(gB + bk);
#pragma unroll
            for (int i = 0; i < 4; i++) { pa[i] = qa[i]; pb[i] = qb[i]; }
        }

        const uint32_t Ab = sb + buf * 16384;
        const uint32_t Bb = sb + 32768 + buf * 16384;
#pragma unroll
        for (int ks = 0; ks < 4; ks++) {
            uint32_t afr[2][4];
#pragma unroll
            for (int mf = 0; mf < 2; mf++)
                ldsm4(afr[mf],
                      Ab + (m0w + mf * 16 + arow) * 128 + ((ks * 32 + acolx) ^ aswz));
            uint32_t bfr[4][4];
#pragma unroll
            for (int nq = 0; nq < 4; nq++)
                ldsm4(bfr[nq],
                      Bb + (n0w + nq * 16 + brow) * 128 + ((ks * 32 + bcolx) ^ bswz));
#pragma unroll
            for (int mf = 0; mf < 2; mf++)
#pragma unroll
                for (int nf = 0; nf < 8; nf++)
                    mma16816(acc[mf][nf], afr[mf],
                             bfr[nf >> 1][(nf & 1) * 2], bfr[nf >> 1][(nf & 1) * 2 + 1]);
        }

        if (pre) {
            const int nb = buf ^ 1;
#pragma unroll
            for (int i = 0; i < 4; i++) {
                uint32_t so = strow + (((uint32_t)(half * 64 + i * 16)) ^ stswz);
                *reinterpret_cast<uint4*>(sm + nb * 16384 + so)         = pa[i];
                *reinterpret_cast<uint4*>(sm + 32768 + nb * 16384 + so) = pb[i];
            }
            __syncthreads();
        }
    }

    // epilogue: registers -> g_Wh
#pragma unroll
    for (int mf = 0; mf < 2; mf++) {
        const int r0 = bm + m0w + mf * 16 + (lane >> 2);
#pragma unroll
        for (int nf = 0; nf < 8; nf++) {
            const int c = bn + n0w + nf * 8 + (lane & 3) * 2;
            *reinterpret_cast<float2*>(g_Wh + (size_t)r0 * OUT_DIM + c) =
                make_float2(acc[mf][nf][0], acc[mf][nf][1]);
            *reinterpret_cast<float2*>(g_Wh + (size_t)(r0 + 8) * OUT_DIM + c) =
                make_float2(acc[mf][nf][2], acc[mf][nf][3]);
        }
    }
}

// ---------------------------------------------------------------------------
// Scores: one warp per (n, head).
// ---------------------------------------------------------------------------
__global__ __launch_bounds__(128) void score_kernel(const float* __restrict__ a) {
    const int n    = blockIdx.x;
    const int h    = threadIdx.x >> 5;
    const int lane = threadIdx.x & 31;
    const float4* row = reinterpret_cast<const float4*>(g_Wh + (size_t)n * OUT_DIM + h * HDIM);
    const float4* a0  = reinterpret_cast<const float4*>(a);
    const float4* a1  = reinterpret_cast<const float4*>(a + HDIM);
    float4 v  = row[lane];
    float4 c0 = a0[lane];
    float4 c1 = a1[lane];
    float ss = v.x * c0.x + v.y * c0.y + v.z * c0.z + v.w * c0.w;
    float sd = v.x * c1.x + v.y * c1.y + v.z * c1.z + v.w * c1.w;
#pragma unroll
    for (int o = 16; o; o >>= 1) {
        ss += __shfl_xor_sync(0xffffffffu, ss, o);
        sd += __shfl_xor_sync(0xffffffffu, sd, o);
    }
    if (lane == 0) {
        g_ssrc[n * NHEADS + h] = ss;
        g_sdst[n * NHEADS + h] = sd;
    }
}

// ---------------------------------------------------------------------------
// Top-16. Lexicographic insertion (val desc, idx asc) — matches jax.lax.top_k.
// ---------------------------------------------------------------------------
__device__ __forceinline__ void insert16(float (&vals)[TOPK], int (&idxs)[TOPK],
                                         float v, int j) {
    if (v > vals[TOPK - 1] || (v == vals[TOPK - 1] && j < idxs[TOPK - 1])) {
        float pv = FLT_MAX;
        int   pi = -1;
#pragma unroll
        for (int s = 0; s < TOPK; s++) {
            float cv = vals[s];
            int   ci = idxs[s];
            bool gp = (v > pv) || (v == pv && j < pi);
            bool gc = (v > cv) || (v == cv && j < ci);
            vals[s] = gp ? pv : (gc ? v : cv);
            idxs[s] = gp ? pi : (gc ? j : ci);
            pv = cv; pi = ci;
        }
    }
}

__global__ __launch_bounds__(128) void topk_kernel(const float* __restrict__ adj) {
    __shared__ int   scnt[4];
    __shared__ float scv[4][MAXC];
    __shared__ int   sci[4][MAXC];

    const int w    = threadIdx.x >> 5;
    const int lane = threadIdx.x & 31;
    const int row  = blockIdx.x * 4 + w;
    const float4* r4 = reinterpret_cast<const float4*>(adj + (size_t)row * N_NODES);

    if (lane == 0) scnt[w] = 0;
    __syncwarp();

    // Pass 1: candidates >= THRESH. 4 independent LDG.128 per iteration
    // (MLP>=4) + one fmax-reduced threshold test per float4.
#pragma unroll 1
    for (int base = 0; base < N_NODES / 4; base += 128) {
        float4 v0 = r4[base + lane];
        float4 v1 = r4[base + lane + 32];
        float4 v2 = r4[base + lane + 64];
        float4 v3 = r4[base + lane + 96];
#pragma unroll
        for (int q = 0; q < 4; q++) {
            float4 v = (q == 0) ? v0 : (q == 1) ? v1 : (q == 2) ? v2 : v3;
            const int j0 = (base + lane + q * 32) * 4;
            float mx = fmaxf(fmaxf(v.x, v.y), fmaxf(v.z, v.w));
            if (mx >= THRESH) {
                if (v.x >= THRESH) { int p = atomicAdd(&scnt[w], 1); if (p < MAXC) { scv[w][p] = v.x; sci[w][p] = j0 + 0; } }
                if (v.y >= THRESH) { int p = atomicAdd(&scnt[w], 1); if (p < MAXC) { scv[w][p] = v.y; sci[w][p] = j0 + 1; } }
                if (v.z >= THRESH) { int p = atomicAdd(&scnt[w], 1); if (p < MAXC) { scv[w][p] = v.z; sci[w][p] = j0 + 2; } }
                if (v.w >= THRESH) { int p = atomicAdd(&scnt[w], 1); if (p < MAXC) { scv[w][p] = v.w; sci[w][p] = j0 + 3; } }
            }
        }
    }
    __syncwarp();
    const int c = scnt[w];

    float vals[TOPK];
    int   idxs[TOPK];
#pragma unroll
    for (int i = 0; i < TOPK; i++) { vals[i] = -FLT_MAX; idxs[i] = 0x7fffffff; }

    if (c >= TOPK && c <= MAXC) {
        for (int t = lane; t < c; t += 32)
            insert16(vals, idxs, scv[w][t], sci[w][t]);
    } else {
        // fallback: exact full scan (arbitrary data safety)
        for (int jj = lane; jj < N_NODES / 4; jj += 32) {
            float4 v = r4[jj];
            const int j0 = jj * 4;
            insert16(vals, idxs, v.x, j0 + 0);
            insert16(vals, idxs, v.y, j0 + 1);
            insert16(vals, idxs, v.z, j0 + 2);
            insert16(vals, idxs, v.w, j0 + 3);
        }
    }

#pragma unroll 1
    for (int t = 0; t < TOPK; t++) {
        float bv = vals[0];
        int   bi = idxs[0];
#pragma unroll
        for (int o = 16; o; o >>= 1) {
            float ov = __shfl_xor_sync(0xffffffffu, bv, o);
            int   oi = __shfl_xor_sync(0xffffffffu, bi, o);
            if (ov > bv || (ov == bv && oi < bi)) { bv = ov; bi = oi; }
        }
        const bool win = (idxs[0] == bi) && (vals[0] == bv);
        if (win) {
#pragma unroll
            for (int s = 0; s < TOPK - 1; s++) {
                vals[s] = vals[s + 1];
                idxs[s] = idxs[s + 1];
            }
            vals[TOPK - 1] = -FLT_MAX;
            idxs[TOPK - 1] = 0x7fffffff;
        }
        if (lane == 0) g_topk[row * TOPK + t] = bi;
    }
}

// ---------------------------------------------------------------------------
// Aggregate: softmax over 16 neighbors, weighted Wh sum, ELU.
// ---------------------------------------------------------------------------
__global__ __launch_bounds__(128) void aggregate_kernel(float* __restrict__ out) {
    const int i   = blockIdx.x;
    const int tid = threadIdx.x;

    __shared__ int   sidx[TOPK];
    __shared__ float salpha[TOPK][NHEADS];

    if (tid < TOPK) sidx[tid] = g_topk[i * TOPK + tid];
    __syncthreads();

    if (tid < TOPK * NHEADS) {
        const int t = tid >> 2, h = tid & 3;
        float e = g_ssrc[i * NHEADS + h] + g_sdst[sidx[t] * NHEADS + h];
        e = (e >= 0.f) ? e : NEG_SLOPE * e;
        salpha[t][h] = e;
    }
    __syncthreads();

    if (tid < NHEADS) {
        const int h = tid;
        float m = -FLT_MAX;
#pragma unroll
        for (int t = 0; t < TOPK; t++) m = fmaxf(m, salpha[t][h]);
        float s = 0.f;
#pragma unroll
        for (int t = 0; t < TOPK; t++) {
            float ex = expf(salpha[t][h] - m);
            salpha[t][h] = ex;
            s += ex;
        }
        float inv = 1.f / s;
#pragma unroll
        for (int t = 0; t < TOPK; t++) salpha[t][h] *= inv;
    }
    __syncthreads();

    const int f = tid;
    const int h = f >> 5;
    float4 acc = make_float4(0.f, 0.f, 0.f, 0.f);
#pragma unroll
    for (int t = 0; t < TOPK; t++) {
        const float4* p = reinterpret_cast<const float4*>(g_Wh + (size_t)sidx[t] * OUT_DIM);
        float4 wv = p[f];
        float al = salpha[t][h];
        acc.x += al * wv.x; acc.y += al * wv.y;
        acc.z += al * wv.z; acc.w += al * wv.w;
    }
    float4 r;
    r.x = (acc.x > 0.f) ? acc.x : expm1f(acc.x);
    r.y = (acc.y > 0.f) ? acc.y : expm1f(acc.y);
    r.z = (acc.z > 0.f) ? acc.z : expm1f(acc.z);
    r.w = (acc.w > 0.f) ? acc.w : expm1f(acc.w);
    reinterpret_cast<float4*>(out + (size_t)i * OUT_DIM)[f] = r;
}

// ---------------------------------------------------------------------------
// Launch: fork the independent {conv_w, topk} chain onto a side stream so it
// overlaps with {conv_x, gemm, score}; join before gemm (needs conv_w) and
// before aggregate (needs topk). Graph-capture-safe: events/streams are
// host-side objects created once; no allocations; same work every call.
// ---------------------------------------------------------------------------
extern "C" void kernel_launch(void* const* d_in, const int* in_sizes, int n_in,
                              void* d_out, int out_size) {
    const float* x   = (const float*)d_in[0];
    const float* adj = (const float*)d_in[1];
    const float* W   = (const float*)d_in[2];
    const float* a   = (const float*)d_in[3];
    float* out = (float*)d_out;

    static cudaStream_t s2 = nullptr;
    static cudaEvent_t ev_fork = nullptr, ev_w = nullptr, ev_topk = nullptr;
    if (s2 == nullptr) {
        cudaStreamCreateWithFlags(&s2, cudaStreamNonBlocking);
        cudaEventCreateWithFlags(&ev_fork, cudaEventDisableTiming);
        cudaEventCreateWithFlags(&ev_w,    cudaEventDisableTiming);
        cudaEventCreateWithFlags(&ev_topk, cudaEventDisableTiming);
        cudaFuncSetAttribute(hmma_gemm_kernel,
                             cudaFuncAttributeMaxDynamicSharedMemorySize, SMEM_DYN);
    }

    // fork side stream off the (captured) main stream
    cudaEventRecord(ev_fork, 0);
    cudaStreamWaitEvent(s2, ev_fork, 0);

    // side branch: conv_w (tiny) then topk (long, independent)
    conv_w_kernel<<<512, 256, 0, s2>>>(W);
    cudaEventRecord(ev_w, s2);
    topk_kernel<<<N_NODES / 4, 128, 0, s2>>>(adj);
    cudaEventRecord(ev_topk, s2);

    // main branch
    conv_x_kernel<<<4096, 256>>>(x);
    cudaStreamWaitEvent(0, ev_w, 0);   // gemm needs g_Bbf
    hmma_gemm_kernel<<<dim3(OUT_DIM / 128, N_NODES / 128), 256, SMEM_DYN>>>();
    score_kernel<<<N_NODES, 128>>>(a);
    cudaStreamWaitEvent(0, ev_topk, 0); // aggregate needs g_topk
    aggregate_kernel<<<N_NODES, 128>>>(out);
}

// round 8
// speedup vs baseline: 7.8617x; 1.0623x over previous
#include <cuda_runtime.h>
#include <cuda_bf16.h>
#include <math.h>
#include <float.h>
#include <stdint.h>

#define N_NODES 4096
#define IN_DIM  1024
#define OUT_DIM 512
#define NHEADS  4
#define HDIM    128
#define TOPK    16
#define NEG_SLOPE 0.2f

#define MAXC   512
#define THRESH 0.98f

#define KC  64          // bf16 per k-chunk (128 B row)
#define NIT 48          // 3072 effective K / 64
#define NSTAGE 4
#define STAGE_BYTES 32768
#define SMEM_DYN (NSTAGE * STAGE_BYTES + 1024)

// Scratch (no cudaMalloc allowed)
__device__ float g_Wh[N_NODES * OUT_DIM];                 // 8 MB
__device__ __nv_bfloat16 g_Abf[(size_t)N_NODES * 2048];   // [x_hi | x_lo]  16 MB
__device__ __nv_bfloat16 g_Bbf[(size_t)OUT_DIM * 2048];   // [W_hi | W_lo]   2 MB
__device__ float g_ssrc[N_NODES * NHEADS];
__device__ float g_sdst[N_NODES * NHEADS];
__device__ int   g_topk[N_NODES * TOPK];

// ---------------------------------------------------------------------------
// helpers
// ---------------------------------------------------------------------------
__device__ __forceinline__ uint32_t smem_to_u32(const void* p) {
    uint32_t a;
    asm("{ .reg .u64 t; cvta.to.shared.u64 t, %1; cvt.u32.u64 %0, t; }"
        : "=r"(a) : "l"(p));
    return a;
}
__device__ __forceinline__ void ldsm4(uint32_t* r, uint32_t addr) {
    asm volatile("ldmatrix.sync.aligned.m8n8.x4.shared.b16 {%0,%1,%2,%3}, [%4];"
        : "=r"(r[0]), "=r"(r[1]), "=r"(r[2]), "=r"(r[3]) : "r"(addr));
}
__device__ __forceinline__ void mma16816(float* d, const uint32_t* a,
                                         uint32_t b0, uint32_t b1) {
    asm volatile("mma.sync.aligned.m16n8k16.row.col.f32.bf16.bf16.f32 "
        "{%0,%1,%2,%3}, {%4,%5,%6,%7}, {%8,%9}, {%0,%1,%2,%3};"
        : "+f"(d[0]), "+f"(d[1]), "+f"(d[2]), "+f"(d[3])
        : "r"(a[0]), "r"(a[1]), "r"(a[2]), "r"(a[3]), "r"(b0), "r"(b1));
}
__device__ __forceinline__ void cpasync16(uint32_t sdst, const void* gsrc) {
    asm volatile("cp.async.cg.shared.global [%0], [%1], 16;"
        :: "r"(sdst), "l"(gsrc));
}
__device__ __forceinline__ void cpasync_commit() {
    asm volatile("cp.async.commit_group;");
}
__device__ __forceinline__ void cpasync_wait2() {
    asm volatile("cp.async.wait_group 2;");
}

// ---------------------------------------------------------------------------
// fp32 -> (hi, lo) bf16 split conversion
// ---------------------------------------------------------------------------
__device__ __forceinline__ void split4(float4 v, uint2& hi, uint2& lo) {
    __nv_bfloat16 hx = __float2bfloat16_rn(v.x), hy = __float2bfloat16_rn(v.y);
    __nv_bfloat16 hz = __float2bfloat16_rn(v.z), hw = __float2bfloat16_rn(v.w);
    float lx = v.x - __bfloat162float(hx), ly = v.y - __bfloat162float(hy);
    float lz = v.z - __bfloat162float(hz), lw = v.w - __bfloat162float(hw);
    __nv_bfloat162 h01 = __halves2bfloat162(hx, hy);
    __nv_bfloat162 h23 = __halves2bfloat162(hz, hw);
    __nv_bfloat162 l01 = __floats2bfloat162_rn(lx, ly);
    __nv_bfloat162 l23 = __floats2bfloat162_rn(lz, lw);
    hi.x = *reinterpret_cast<uint32_t*>(&h01); hi.y = *reinterpret_cast<uint32_t*>(&h23);
    lo.x = *reinterpret_cast<uint32_t*>(&l01); lo.y = *reinterpret_cast<uint32_t*>(&l23);
}

__global__ __launch_bounds__(256) void conv_x_kernel(const float* __restrict__ x) {
    int i = blockIdx.x * 256 + threadIdx.x;      // float4 index
    float4 v = reinterpret_cast<const float4*>(x)[i];
    int r = i >> 8, c4 = i & 255;
    uint2 hi, lo; split4(v, hi, lo);
    __nv_bfloat16* base = g_Abf + (size_t)r * 2048 + c4 * 4;
    *reinterpret_cast<uint2*>(base)        = hi;
    *reinterpret_cast<uint2*>(base + 1024) = lo;
}
__global__ __launch_bounds__(256) void conv_w_kernel(const float* __restrict__ W) {
    int i = blockIdx.x * 256 + threadIdx.x;
    float4 v = reinterpret_cast<const float4*>(W)[i];
    int r = i >> 8, c4 = i & 255;
    uint2 hi, lo; split4(v, hi, lo);
    __nv_bfloat16* base = g_Bbf + (size_t)r * 2048 + c4 * 4;
    *reinterpret_cast<uint2*>(base)        = hi;
    *reinterpret_cast<uint2*>(base + 1024) = lo;
}

// ---------------------------------------------------------------------------
// HMMA GEMM + fused score. Wh = x @ W^T via bf16x3, fp32 accum.
// 128x128 CTA tile; CTA column == head (TN == HDIM == 128), so the score
// dot-products for this CTA's rows are reduced entirely in-CTA (no atomics
// to global). cp.async 4-stage pipeline, one syncthreads per k-iter.
// ---------------------------------------------------------------------------
__global__ __launch_bounds__(256, 1) void hmma_gemm_kernel(const float* __restrict__ a) {
    extern __shared__ char smem_raw[];
    char* sm = (char*)(((uintptr_t)smem_raw + 1023) & ~(uintptr_t)1023);
    const uint32_t sb = smem_to_u32(sm);
    __shared__ float sa[2 * HDIM];     // a_src | a_dst
    __shared__ float ssum[2 * 128];    // per-row src | dst partials

    const int tid  = threadIdx.x;
    const int wid  = tid >> 5;
    const int lane = tid & 31;
    const int bm = blockIdx.y * 128;
    const int bn = blockIdx.x * 128;
    const int m0w = (wid & 3) * 32;
    const int n0w = (wid >> 2) * 64;

    if (tid < 2 * HDIM) sa[tid] = a[tid];

    // loader mapping: 256 threads cover 128 rows x 128 B; 4 x 16 B each
    const int row  = tid >> 1;
    const int half = tid & 1;
    const __nv_bfloat16* gA = g_Abf + (size_t)(bm + row) * 2048 + half * 32;
    const __nv_bfloat16* gB = g_Bbf + (size_t)(bn + row) * 2048 + half * 32;
    const uint32_t strow = (uint32_t)row * 128;
    const uint32_t stswz = ((uint32_t)row & 7) << 4;

    // ldmatrix per-lane constants
    const uint32_t arow  = lane & 15;
    const uint32_t acolx = (lane & 16) ? 16u : 0u;
    const uint32_t aswz  = (arow & 7) << 4;
    const uint32_t brow  = (lane & 7) + ((lane & 16) >> 1);
    const uint32_t bcolx = (lane & 8) ? 16u : 0u;
    const uint32_t bswz  = (brow & 7) << 4;

    float acc[2][8][4] = {};

    // issue stage s (k-chunk s) into buffer s % NSTAGE
    auto issue_stage = [&](int s) {
        const int ak = (s < 32) ? s * KC : (s - 32) * KC;
        const int bk = (s < 16) ? s * KC
                     : ((s < 32) ? (s - 16) * KC : 1024 + (s - 32) * KC);
        const uint32_t base = sb + (uint32_t)(s & (NSTAGE - 1)) * STAGE_BYTES;
#pragma unroll
        for (int i = 0; i < 4; i++) {
            const uint32_t so = strow + (((uint32_t)(half * 64 + i * 16)) ^ stswz);
            cpasync16(base + so,         gA + ak + i * 8);
            cpasync16(base + 16384 + so, gB + bk + i * 8);
        }
    };

    // prologue: 3 stages in flight
#pragma unroll
    for (int s = 0; s < 3; s++) { issue_stage(s); cpasync_commit(); }

#pragma unroll 1
    for (int it = 0; it < NIT; it++) {
        cpasync_wait2();            // stage `it` resident
        __syncthreads();            // all warps done with stage it-1 reads

        if (it + 3 < NIT) issue_stage(it + 3);
        cpasync_commit();           // empty group in the tail keeps count uniform

        const uint32_t Ab = sb + (uint32_t)(it & (NSTAGE - 1)) * STAGE_BYTES;
        const uint32_t Bb = Ab + 16384;
#pragma unroll
        for (int ks = 0; ks < 4; ks++) {
            uint32_t afr[2][4];
#pragma unroll
            for (int mf = 0; mf < 2; mf++)
                ldsm4(afr[mf],
                      Ab + (m0w + mf * 16 + arow) * 128 + ((ks * 32 + acolx) ^ aswz));
            uint32_t bfr[4][4];
#pragma unroll
            for (int nq = 0; nq < 4; nq++)
                ldsm4(bfr[nq],
                      Bb + (n0w + nq * 16 + brow) * 128 + ((ks * 32 + bcolx) ^ bswz));
#pragma unroll
            for (int mf = 0; mf < 2; mf++)
#pragma unroll
                for (int nf = 0; nf < 8; nf++)
                    mma16816(acc[mf][nf], afr[mf],
                             bfr[nf >> 1][(nf & 1) * 2], bfr[nf >> 1][(nf & 1) * 2 + 1]);
        }
    }

    // ---- epilogue 1: Wh tile to global ----
#pragma unroll
    for (int mf = 0; mf < 2; mf++) {
        const int r0 = bm + m0w + mf * 16 + (lane >> 2);
#pragma unroll
        for (int nf = 0; nf < 8; nf++) {
            const int c = bn + n0w + nf * 8 + (lane & 3) * 2;
            *reinterpret_cast<float2*>(g_Wh + (size_t)r0 * OUT_DIM + c) =
                make_float2(acc[mf][nf][0], acc[mf][nf][1]);
            *reinterpret_cast<float2*>(g_Wh + (size_t)(r0 + 8) * OUT_DIM + c) =
                make_float2(acc[mf][nf][2], acc[mf][nf][3]);
        }
    }

    // ---- epilogue 2: fused score (this CTA owns head h = blockIdx.x) ----
    __syncthreads();
    if (tid < 256) ssum[tid] = 0.f;
    __syncthreads();

    float sp[2][2] = {}, dp[2][2] = {};   // [mf][rowhalf]
#pragma unroll
    for (int nf = 0; nf < 8; nf++) {
        const int c = n0w + nf * 8 + (lane & 3) * 2;   // 0..127 within head
        const float a0s = sa[c],        a1s = sa[c + 1];
        const float a0d = sa[HDIM + c], a1d = sa[HDIM + c + 1];
#pragma unroll
        for (int mf = 0; mf < 2; mf++) {
            sp[mf][0] += acc[mf][nf][0] * a0s + acc[mf][nf][1] * a1s;
            sp[mf][1] += acc[mf][nf][2] * a0s + acc[mf][nf][3] * a1s;
            dp[mf][0] += acc[mf][nf][0] * a0d + acc[mf][nf][1] * a1d;
            dp[mf][1] += acc[mf][nf][2] * a0d + acc[mf][nf][3] * a1d;
        }
    }
#pragma unroll
    for (int o = 1; o <= 2; o <<= 1) {
#pragma unroll
        for (int mf = 0; mf < 2; mf++)
#pragma unroll
            for (int r = 0; r < 2; r++) {
                sp[mf][r] += __shfl_xor_sync(0xffffffffu, sp[mf][r], o);
                dp[mf][r] += __shfl_xor_sync(0xffffffffu, dp[mf][r], o);
            }
    }
    if ((lane & 3) == 0) {
#pragma unroll
        for (int mf = 0; mf < 2; mf++)
#pragma unroll
            for (int r = 0; r < 2; r++) {
                const int rt = m0w + mf * 16 + (lane >> 2) + r * 8;
                atomicAdd(&ssum[rt], sp[mf][r]);
                atomicAdd(&ssum[128 + rt], dp[mf][r]);
            }
    }
    __syncthreads();
    if (tid < 128) {
        const int h = blockIdx.x;                      // head index
        g_ssrc[(bm + tid) * NHEADS + h] = ssum[tid];
        g_sdst[(bm + tid) * NHEADS + h] = ssum[128 + tid];
    }
}

// ---------------------------------------------------------------------------
// Top-16. Lexicographic insertion (val desc, idx asc) — matches jax.lax.top_k.
// ---------------------------------------------------------------------------
__device__ __forceinline__ void insert16(float (&vals)[TOPK], int (&idxs)[TOPK],
                                         float v, int j) {
    if (v > vals[TOPK - 1] || (v == vals[TOPK - 1] && j < idxs[TOPK - 1])) {
        float pv = FLT_MAX;
        int   pi = -1;
#pragma unroll
        for (int s = 0; s < TOPK; s++) {
            float cv = vals[s];
            int   ci = idxs[s];
            bool gp = (v > pv) || (v == pv && j < pi);
            bool gc = (v > cv) || (v == cv && j < ci);
            vals[s] = gp ? pv : (gc ? v : cv);
            idxs[s] = gp ? pi : (gc ? j : ci);
            pv = cv; pi = ci;
        }
    }
}

__global__ __launch_bounds__(128) void topk_kernel(const float* __restrict__ adj) {
    __shared__ int   scnt[4];
    __shared__ float scv[4][MAXC];
    __shared__ int   sci[4][MAXC];

    const int w    = threadIdx.x >> 5;
    const int lane = threadIdx.x & 31;
    const int row  = blockIdx.x * 4 + w;
    const float4* r4 = reinterpret_cast<const float4*>(adj + (size_t)row * N_NODES);

    if (lane == 0) scnt[w] = 0;
    __syncwarp();

#pragma unroll 1
    for (int base = 0; base < N_NODES / 4; base += 128) {
        float4 v0 = r4[base + lane];
        float4 v1 = r4[base + lane + 32];
        float4 v2 = r4[base + lane + 64];
        float4 v3 = r4[base + lane + 96];
#pragma unroll
        for (int q = 0; q < 4; q++) {
            float4 v = (q == 0) ? v0 : (q == 1) ? v1 : (q == 2) ? v2 : v3;
            const int j0 = (base + lane + q * 32) * 4;
            float mx = fmaxf(fmaxf(v.x, v.y), fmaxf(v.z, v.w));
            if (mx >= THRESH) {
                if (v.x >= THRESH) { int p = atomicAdd(&scnt[w], 1); if (p < MAXC) { scv[w][p] = v.x; sci[w][p] = j0 + 0; } }
                if (v.y >= THRESH) { int p = atomicAdd(&scnt[w], 1); if (p < MAXC) { scv[w][p] = v.y; sci[w][p] = j0 + 1; } }
                if (v.z >= THRESH) { int p = atomicAdd(&scnt[w], 1); if (p < MAXC) { scv[w][p] = v.z; sci[w][p] = j0 + 2; } }
                if (v.w >= THRESH) { int p = atomicAdd(&scnt[w], 1); if (p < MAXC) { scv[w][p] = v.w; sci[w][p] = j0 + 3; } }
            }
        }
    }
    __syncwarp();
    const int c = scnt[w];

    float vals[TOPK];
    int   idxs[TOPK];
#pragma unroll
    for (int i = 0; i < TOPK; i++) { vals[i] = -FLT_MAX; idxs[i] = 0x7fffffff; }

    if (c >= TOPK && c <= MAXC) {
        for (int t = lane; t < c; t += 32)
            insert16(vals, idxs, scv[w][t], sci[w][t]);
    } else {
        for (int jj = lane; jj < N_NODES / 4; jj += 32) {
            float4 v = r4[jj];
            const int j0 = jj * 4;
            insert16(vals, idxs, v.x, j0 + 0);
            insert16(vals, idxs, v.y, j0 + 1);
            insert16(vals, idxs, v.z, j0 + 2);
            insert16(vals, idxs, v.w, j0 + 3);
        }
    }

#pragma unroll 1
    for (int t = 0; t < TOPK; t++) {
        float bv = vals[0];
        int   bi = idxs[0];
#pragma unroll
        for (int o = 16; o; o >>= 1) {
            float ov = __shfl_xor_sync(0xffffffffu, bv, o);
            int   oi = __shfl_xor_sync(0xffffffffu, bi, o);
            if (ov > bv || (ov == bv && oi < bi)) { bv = ov; bi = oi; }
        }
        const bool win = (idxs[0] == bi) && (vals[0] == bv);
        if (win) {
#pragma unroll
            for (int s = 0; s < TOPK - 1; s++) {
                vals[s] = vals[s + 1];
                idxs[s] = idxs[s + 1];
            }
            vals[TOPK - 1] = -FLT_MAX;
            idxs[TOPK - 1] = 0x7fffffff;
        }
        if (lane == 0) g_topk[row * TOPK + t] = bi;
    }
}

// ---------------------------------------------------------------------------
// Aggregate: softmax over 16 neighbors, weighted Wh sum, ELU.
// ---------------------------------------------------------------------------
__global__ __launch_bounds__(128) void aggregate_kernel(float* __restrict__ out) {
    const int i   = blockIdx.x;
    const int tid = threadIdx.x;

    __shared__ int   sidx[TOPK];
    __shared__ float salpha[TOPK][NHEADS];

    if (tid < TOPK) sidx[tid] = g_topk[i * TOPK + tid];
    __syncthreads();

    if (tid < TOPK * NHEADS) {
        const int t = tid >> 2, h = tid & 3;
        float e = g_ssrc[i * NHEADS + h] + g_sdst[sidx[t] * NHEADS + h];
        e = (e >= 0.f) ? e : NEG_SLOPE * e;
        salpha[t][h] = e;
    }
    __syncthreads();

    if (tid < NHEADS) {
        const int h = tid;
        float m = -FLT_MAX;
#pragma unroll
        for (int t = 0; t < TOPK; t++) m = fmaxf(m, salpha[t][h]);
        float s = 0.f;
#pragma unroll
        for (int t = 0; t < TOPK; t++) {
            float ex = expf(salpha[t][h] - m);
            salpha[t][h] = ex;
            s += ex;
        }
        float inv = 1.f / s;
#pragma unroll
        for (int t = 0; t < TOPK; t++) salpha[t][h] *= inv;
    }
    __syncthreads();

    const int f = tid;
    const int h = f >> 5;
    float4 acc = make_float4(0.f, 0.f, 0.f, 0.f);
#pragma unroll
    for (int t = 0; t < TOPK; t++) {
        const float4* p = reinterpret_cast<const float4*>(g_Wh + (size_t)sidx[t] * OUT_DIM);
        float4 wv = p[f];
        float al = salpha[t][h];
        acc.x += al * wv.x; acc.y += al * wv.y;
        acc.z += al * wv.z; acc.w += al * wv.w;
    }
    float4 r;
    r.x = (acc.x > 0.f) ? acc.x : expm1f(acc.x);
    r.y = (acc.y > 0.f) ? acc.y : expm1f(acc.y);
    r.z = (acc.z > 0.f) ? acc.z : expm1f(acc.z);
    r.w = (acc.w > 0.f) ? acc.w : expm1f(acc.w);
    reinterpret_cast<float4*>(out + (size_t)i * OUT_DIM)[f] = r;
}

// ---------------------------------------------------------------------------
// Launch: fork {conv_w, topk} onto a side stream; join before gemm (needs
// conv_w) and before aggregate (needs topk). Score is fused into the gemm.
// ---------------------------------------------------------------------------
extern "C" void kernel_launch(void* const* d_in, const int* in_sizes, int n_in,
                              void* d_out, int out_size) {
    const float* x   = (const float*)d_in[0];
    const float* adj = (const float*)d_in[1];
    const float* W   = (const float*)d_in[2];
    const float* a   = (const float*)d_in[3];
    float* out = (float*)d_out;

    static cudaStream_t s2 = nullptr;
    static cudaEvent_t ev_fork = nullptr, ev_w = nullptr, ev_topk = nullptr;
    if (s2 == nullptr) {
        cudaStreamCreateWithFlags(&s2, cudaStreamNonBlocking);
        cudaEventCreateWithFlags(&ev_fork, cudaEventDisableTiming);
        cudaEventCreateWithFlags(&ev_w,    cudaEventDisableTiming);
        cudaEventCreateWithFlags(&ev_topk, cudaEventDisableTiming);
        cudaFuncSetAttribute(hmma_gemm_kernel,
                             cudaFuncAttributeMaxDynamicSharedMemorySize, SMEM_DYN);
    }

    cudaEventRecord(ev_fork, 0);
    cudaStreamWaitEvent(s2, ev_fork, 0);

    conv_w_kernel<<<512, 256, 0, s2>>>(W);
    cudaEventRecord(ev_w, s2);
    topk_kernel<<<N_NODES / 4, 128, 0, s2>>>(adj);
    cudaEventRecord(ev_topk, s2);

    conv_x_kernel<<<4096, 256>>>(x);
    cudaStreamWaitEvent(0, ev_w, 0);
    hmma_gemm_kernel<<<dim3(OUT_DIM / 128, N_NODES / 128), 256, SMEM_DYN>>>(a);
    cudaStreamWaitEvent(0, ev_topk, 0);
    aggregate_kernel<<<N_NODES, 128>>>(out);
}

// round 9
// speedup vs baseline: 8.4708x; 1.0775x over previous
#include <cuda_runtime.h>
#include <cuda_bf16.h>
#include <math.h>
#include <float.h>
#include <stdint.h>

#define N_NODES 4096
#define IN_DIM  1024
#define OUT_DIM 512
#define NHEADS  4
#define HDIM    128
#define TOPK    16
#define NEG_SLOPE 0.2f

#define MAXC   512
#define THRESH 0.98f

#define KC  64          // bf16 per k-chunk (128 B row)
#define NIT 48          // 3072 effective K / 64
#define NSTAGE 4
#define STAGE_BYTES 32768
#define SMEM_DYN (NSTAGE * STAGE_BYTES + 1024)

// Scratch (no cudaMalloc allowed)
__device__ float g_Wh[N_NODES * OUT_DIM];                 // 8 MB
__device__ __nv_bfloat16 g_Abf[(size_t)N_NODES * 2048];   // [x_hi | x_lo]  16 MB
__device__ __nv_bfloat16 g_Bbf[(size_t)OUT_DIM * 2048];   // [W_hi | W_lo]   2 MB
__device__ float g_ssrc[N_NODES * NHEADS];
__device__ float g_sdst[N_NODES * NHEADS];
__device__ int   g_topk[N_NODES * TOPK];

// ---------------------------------------------------------------------------
// helpers
// ---------------------------------------------------------------------------
__device__ __forceinline__ uint32_t smem_to_u32(const void* p) {
    uint32_t a;
    asm("{ .reg .u64 t; cvta.to.shared.u64 t, %1; cvt.u32.u64 %0, t; }"
        : "=r"(a) : "l"(p));
    return a;
}
__device__ __forceinline__ void ldsm4(uint32_t* r, uint32_t addr) {
    asm volatile("ldmatrix.sync.aligned.m8n8.x4.shared.b16 {%0,%1,%2,%3}, [%4];"
        : "=r"(r[0]), "=r"(r[1]), "=r"(r[2]), "=r"(r[3]) : "r"(addr));
}
__device__ __forceinline__ void mma16816(float* d, const uint32_t* a,
                                         uint32_t b0, uint32_t b1) {
    asm volatile("mma.sync.aligned.m16n8k16.row.col.f32.bf16.bf16.f32 "
        "{%0,%1,%2,%3}, {%4,%5,%6,%7}, {%8,%9}, {%0,%1,%2,%3};"
        : "+f"(d[0]), "+f"(d[1]), "+f"(d[2]), "+f"(d[3])
        : "r"(a[0]), "r"(a[1]), "r"(a[2]), "r"(a[3]), "r"(b0), "r"(b1));
}
__device__ __forceinline__ void cpasync16(uint32_t sdst, const void* gsrc) {
    asm volatile("cp.async.cg.shared.global [%0], [%1], 16;"
        :: "r"(sdst), "l"(gsrc));
}
__device__ __forceinline__ void cpasync_commit() {
    asm volatile("cp.async.commit_group;");
}
__device__ __forceinline__ void cpasync_wait2() {
    asm volatile("cp.async.wait_group 2;");
}

// ---------------------------------------------------------------------------
// fp32 -> (hi, lo) bf16 split conversion
// ---------------------------------------------------------------------------
__device__ __forceinline__ void split4(float4 v, uint2& hi, uint2& lo) {
    __nv_bfloat16 hx = __float2bfloat16_rn(v.x), hy = __float2bfloat16_rn(v.y);
    __nv_bfloat16 hz = __float2bfloat16_rn(v.z), hw = __float2bfloat16_rn(v.w);
    float lx = v.x - __bfloat162float(hx), ly = v.y - __bfloat162float(hy);
    float lz = v.z - __bfloat162float(hz), lw = v.w - __bfloat162float(hw);
    __nv_bfloat162 h01 = __halves2bfloat162(hx, hy);
    __nv_bfloat162 h23 = __halves2bfloat162(hz, hw);
    __nv_bfloat162 l01 = __floats2bfloat162_rn(lx, ly);
    __nv_bfloat162 l23 = __floats2bfloat162_rn(lz, lw);
    hi.x = *reinterpret_cast<uint32_t*>(&h01); hi.y = *reinterpret_cast<uint32_t*>(&h23);
    lo.x = *reinterpret_cast<uint32_t*>(&l01); lo.y = *reinterpret_cast<uint32_t*>(&l23);
}

__global__ __launch_bounds__(256) void conv_x_kernel(const float* __restrict__ x) {
    int i = blockIdx.x * 256 + threadIdx.x;      // float4 index
    float4 v = reinterpret_cast<const float4*>(x)[i];
    int r = i >> 8, c4 = i & 255;
    uint2 hi, lo; split4(v, hi, lo);
    __nv_bfloat16* base = g_Abf + (size_t)r * 2048 + c4 * 4;
    *reinterpret_cast<uint2*>(base)        = hi;
    *reinterpret_cast<uint2*>(base + 1024) = lo;
}
__global__ __launch_bounds__(256) void conv_w_kernel(const float* __restrict__ W) {
    int i = blockIdx.x * 256 + threadIdx.x;
    float4 v = reinterpret_cast<const float4*>(W)[i];
    int r = i >> 8, c4 = i & 255;
    uint2 hi, lo; split4(v, hi, lo);
    __nv_bfloat16* base = g_Bbf + (size_t)r * 2048 + c4 * 4;
    *reinterpret_cast<uint2*>(base)        = hi;
    *reinterpret_cast<uint2*>(base + 1024) = lo;
}

// ---------------------------------------------------------------------------
// HMMA GEMM + fused score. 512 threads / 16 warps, warp tile 32x32
// (4x4 warp grid over 128x128 CTA tile) for SMSP latency hiding.
// cp.async 4-stage pipeline; CTA column == head, score reduced in-CTA.
// ---------------------------------------------------------------------------
__global__ __launch_bounds__(512, 1) void hmma_gemm_kernel(const float* __restrict__ a) {
    extern __shared__ char smem_raw[];
    char* sm = (char*)(((uintptr_t)smem_raw + 1023) & ~(uintptr_t)1023);
    const uint32_t sb = smem_to_u32(sm);
    __shared__ float sa[2 * HDIM];     // a_src | a_dst
    __shared__ float ssum[2 * 128];    // per-row src | dst partials

    const int tid  = threadIdx.x;
    const int wid  = tid >> 5;
    const int lane = tid & 31;
    const int bm = blockIdx.y * 128;
    const int bn = blockIdx.x * 128;
    const int m0w = (wid & 3) * 32;    // warp m origin
    const int n0w = (wid >> 2) * 32;   // warp n origin

    if (tid < 2 * HDIM) sa[tid] = a[tid];

    // loader mapping: 512 threads cover 128 rows x 128 B; 2 x 16 B each
    const int row  = tid >> 2;
    const int quar = tid & 3;          // 32-byte chunk within row
    const __nv_bfloat16* gA = g_Abf + (size_t)(bm + row) * 2048 + quar * 16;
    const __nv_bfloat16* gB = g_Bbf + (size_t)(bn + row) * 2048 + quar * 16;
    const uint32_t strow = (uint32_t)row * 128;
    const uint32_t stswz = ((uint32_t)row & 7) << 4;

    // ldmatrix per-lane constants (SW128, 128 B rows)
    const uint32_t arow  = lane & 15;
    const uint32_t acolx = (lane & 16) ? 16u : 0u;
    const uint32_t aswz  = (arow & 7) << 4;
    const uint32_t brow  = (lane & 7) + ((lane & 16) >> 1);
    const uint32_t bcolx = (lane & 8) ? 16u : 0u;
    const uint32_t bswz  = (brow & 7) << 4;

    float acc[2][4][4] = {};

    auto issue_stage = [&](int s) {
        const int ak = (s < 32) ? s * KC : (s - 32) * KC;
        const int bk = (s < 16) ? s * KC
                     : ((s < 32) ? (s - 16) * KC : 1024 + (s - 32) * KC);
        const uint32_t base = sb + (uint32_t)(s & (NSTAGE - 1)) * STAGE_BYTES;
#pragma unroll
        for (int i = 0; i < 2; i++) {
            const uint32_t so = strow + (((uint32_t)(quar * 32 + i * 16)) ^ stswz);
            cpasync16(base + so,         gA + ak + i * 8);
            cpasync16(base + 16384 + so, gB + bk + i * 8);
        }
    };

#pragma unroll
    for (int s = 0; s < 3; s++) { issue_stage(s); cpasync_commit(); }

#pragma unroll 1
    for (int it = 0; it < NIT; it++) {
        cpasync_wait2();
        __syncthreads();

        if (it + 3 < NIT) issue_stage(it + 3);
        cpasync_commit();

        const uint32_t Ab = sb + (uint32_t)(it & (NSTAGE - 1)) * STAGE_BYTES;
        const uint32_t Bb = Ab + 16384;
#pragma unroll
        for (int ks = 0; ks < 4; ks++) {
            uint32_t afr[2][4];
#pragma unroll
            for (int mf = 0; mf < 2; mf++)
                ldsm4(afr[mf],
                      Ab + (m0w + mf * 16 + arow) * 128 + ((ks * 32 + acolx) ^ aswz));
            uint32_t bfr[2][4];
#pragma unroll
            for (int nq = 0; nq < 2; nq++)
                ldsm4(bfr[nq],
                      Bb + (n0w + nq * 16 + brow) * 128 + ((ks * 32 + bcolx) ^ bswz));
#pragma unroll
            for (int mf = 0; mf < 2; mf++)
#pragma unroll
                for (int nf = 0; nf < 4; nf++)
                    mma16816(acc[mf][nf], afr[mf],
                             bfr[nf >> 1][(nf & 1) * 2], bfr[nf >> 1][(nf & 1) * 2 + 1]);
        }
    }

    // ---- epilogue 1: Wh tile to global ----
#pragma unroll
    for (int mf = 0; mf < 2; mf++) {
        const int r0 = bm + m0w + mf * 16 + (lane >> 2);
#pragma unroll
        for (int nf = 0; nf < 4; nf++) {
            const int c = bn + n0w + nf * 8 + (lane & 3) * 2;
            *reinterpret_cast<float2*>(g_Wh + (size_t)r0 * OUT_DIM + c) =
                make_float2(acc[mf][nf][0], acc[mf][nf][1]);
            *reinterpret_cast<float2*>(g_Wh + (size_t)(r0 + 8) * OUT_DIM + c) =
                make_float2(acc[mf][nf][2], acc[mf][nf][3]);
        }
    }

    // ---- epilogue 2: fused score (CTA owns head h = blockIdx.x) ----
    __syncthreads();
    if (tid < 256) ssum[tid] = 0.f;
    __syncthreads();

    float sp[2][2] = {}, dp[2][2] = {};   // [mf][rowhalf]
#pragma unroll
    for (int nf = 0; nf < 4; nf++) {
        const int c = n0w + nf * 8 + (lane & 3) * 2;   // 0..127 within head
        const float a0s = sa[c],        a1s = sa[c + 1];
        const float a0d = sa[HDIM + c], a1d = sa[HDIM + c + 1];
#pragma unroll
        for (int mf = 0; mf < 2; mf++) {
            sp[mf][0] += acc[mf][nf][0] * a0s + acc[mf][nf][1] * a1s;
            sp[mf][1] += acc[mf][nf][2] * a0s + acc[mf][nf][3] * a1s;
            dp[mf][0] += acc[mf][nf][0] * a0d + acc[mf][nf][1] * a1d;
            dp[mf][1] += acc[mf][nf][2] * a0d + acc[mf][nf][3] * a1d;
        }
    }
#pragma unroll
    for (int o = 1; o <= 2; o <<= 1) {
#pragma unroll
        for (int mf = 0; mf < 2; mf++)
#pragma unroll
            for (int r = 0; r < 2; r++) {
                sp[mf][r] += __shfl_xor_sync(0xffffffffu, sp[mf][r], o);
                dp[mf][r] += __shfl_xor_sync(0xffffffffu, dp[mf][r], o);
            }
    }
    if ((lane & 3) == 0) {
#pragma unroll
        for (int mf = 0; mf < 2; mf++)
#pragma unroll
            for (int r = 0; r < 2; r++) {
                const int rt = m0w + mf * 16 + (lane >> 2) + r * 8;
                atomicAdd(&ssum[rt], sp[mf][r]);
                atomicAdd(&ssum[128 + rt], dp[mf][r]);
            }
    }
    __syncthreads();
    if (tid < 128) {
        const int h = blockIdx.x;
        g_ssrc[(bm + tid) * NHEADS + h] = ssum[tid];
        g_sdst[(bm + tid) * NHEADS + h] = ssum[128 + tid];
    }
}

// ---------------------------------------------------------------------------
// Top-16. Lexicographic insertion (val desc, idx asc) — matches jax.lax.top_k.
// ---------------------------------------------------------------------------
__device__ __forceinline__ void insert16(float (&vals)[TOPK], int (&idxs)[TOPK],
                                         float v, int j) {
    if (v > vals[TOPK - 1] || (v == vals[TOPK - 1] && j < idxs[TOPK - 1])) {
        float pv = FLT_MAX;
        int   pi = -1;
#pragma unroll
        for (int s = 0; s < TOPK; s++) {
            float cv = vals[s];
            int   ci = idxs[s];
            bool gp = (v > pv) || (v == pv && j < pi);
            bool gc = (v > cv) || (v == cv && j < ci);
            vals[s] = gp ? pv : (gc ? v : cv);
            idxs[s] = gp ? pi : (gc ? j : ci);
            pv = cv; pi = ci;
        }
    }
}

__global__ __launch_bounds__(128) void topk_kernel(const float* __restrict__ adj) {
    __shared__ int   scnt[4];
    __shared__ float scv[4][MAXC];
    __shared__ int   sci[4][MAXC];

    const int w    = threadIdx.x >> 5;
    const int lane = threadIdx.x & 31;
    const int row  = blockIdx.x * 4 + w;
    const float4* r4 = reinterpret_cast<const float4*>(adj + (size_t)row * N_NODES);

    if (lane == 0) scnt[w] = 0;
    __syncwarp();

#pragma unroll 1
    for (int base = 0; base < N_NODES / 4; base += 128) {
        float4 v0 = r4[base + lane];
        float4 v1 = r4[base + lane + 32];
        float4 v2 = r4[base + lane + 64];
        float4 v3 = r4[base + lane + 96];
#pragma unroll
        for (int q = 0; q < 4; q++) {
            float4 v = (q == 0) ? v0 : (q == 1) ? v1 : (q == 2) ? v2 : v3;
            const int j0 = (base + lane + q * 32) * 4;
            float mx = fmaxf(fmaxf(v.x, v.y), fmaxf(v.z, v.w));
            if (mx >= THRESH) {
                if (v.x >= THRESH) { int p = atomicAdd(&scnt[w], 1); if (p < MAXC) { scv[w][p] = v.x; sci[w][p] = j0 + 0; } }
                if (v.y >= THRESH) { int p = atomicAdd(&scnt[w], 1); if (p < MAXC) { scv[w][p] = v.y; sci[w][p] = j0 + 1; } }
                if (v.z >= THRESH) { int p = atomicAdd(&scnt[w], 1); if (p < MAXC) { scv[w][p] = v.z; sci[w][p] = j0 + 2; } }
                if (v.w >= THRESH) { int p = atomicAdd(&scnt[w], 1); if (p < MAXC) { scv[w][p] = v.w; sci[w][p] = j0 + 3; } }
            }
        }
    }
    __syncwarp();
    const int c = scnt[w];

    float vals[TOPK];
    int   idxs[TOPK];
#pragma unroll
    for (int i = 0; i < TOPK; i++) { vals[i] = -FLT_MAX; idxs[i] = 0x7fffffff; }

    if (c >= TOPK && c <= MAXC) {
        for (int t = lane; t < c; t += 32)
            insert16(vals, idxs, scv[w][t], sci[w][t]);
    } else {
        for (int jj = lane; jj < N_NODES / 4; jj += 32) {
            float4 v = r4[jj];
            const int j0 = jj * 4;
            insert16(vals, idxs, v.x, j0 + 0);
            insert16(vals, idxs, v.y, j0 + 1);
            insert16(vals, idxs, v.z, j0 + 2);
            insert16(vals, idxs, v.w, j0 + 3);
        }
    }

#pragma unroll 1
    for (int t = 0; t < TOPK; t++) {
        float bv = vals[0];
        int   bi = idxs[0];
#pragma unroll
        for (int o = 16; o; o >>= 1) {
            float ov = __shfl_xor_sync(0xffffffffu, bv, o);
            int   oi = __shfl_xor_sync(0xffffffffu, bi, o);
            if (ov > bv || (ov == bv && oi < bi)) { bv = ov; bi = oi; }
        }
        const bool win = (idxs[0] == bi) && (vals[0] == bv);
        if (win) {
#pragma unroll
            for (int s = 0; s < TOPK - 1; s++) {
                vals[s] = vals[s + 1];
                idxs[s] = idxs[s + 1];
            }
            vals[TOPK - 1] = -FLT_MAX;
            idxs[TOPK - 1] = 0x7fffffff;
        }
        if (lane == 0) g_topk[row * TOPK + t] = bi;
    }
}

// ---------------------------------------------------------------------------
// Aggregate: softmax over 16 neighbors, weighted Wh sum, ELU.
// ---------------------------------------------------------------------------
__global__ __launch_bounds__(128) void aggregate_kernel(float* __restrict__ out) {
    const int i   = blockIdx.x;
    const int tid = threadIdx.x;

    __shared__ int   sidx[TOPK];
    __shared__ float salpha[TOPK][NHEADS];

    if (tid < TOPK) sidx[tid] = g_topk[i * TOPK + tid];
    __syncthreads();

    if (tid < TOPK * NHEADS) {
        const int t = tid >> 2, h = tid & 3;
        float e = g_ssrc[i * NHEADS + h] + g_sdst[sidx[t] * NHEADS + h];
        e = (e >= 0.f) ? e : NEG_SLOPE * e;
        salpha[t][h] = e;
    }
    __syncthreads();

    if (tid < NHEADS) {
        const int h = tid;
        float m = -FLT_MAX;
#pragma unroll
        for (int t = 0; t < TOPK; t++) m = fmaxf(m, salpha[t][h]);
        float s = 0.f;
#pragma unroll
        for (int t = 0; t < TOPK; t++) {
            float ex = expf(salpha[t][h] - m);
            salpha[t][h] = ex;
            s += ex;
        }
        float inv = 1.f / s;
#pragma unroll
        for (int t = 0; t < TOPK; t++) salpha[t][h] *= inv;
    }
    __syncthreads();

    const int f = tid;
    const int h = f >> 5;
    float4 acc = make_float4(0.f, 0.f, 0.f, 0.f);
#pragma unroll
    for (int t = 0; t < TOPK; t++) {
        const float4* p = reinterpret_cast<const float4*>(g_Wh + (size_t)sidx[t] * OUT_DIM);
        float4 wv = p[f];
        float al = salpha[t][h];
        acc.x += al * wv.x; acc.y += al * wv.y;
        acc.z += al * wv.z; acc.w += al * wv.w;
    }
    float4 r;
    r.x = (acc.x > 0.f) ? acc.x : expm1f(acc.x);
    r.y = (acc.y > 0.f) ? acc.y : expm1f(acc.y);
    r.z = (acc.z > 0.f) ? acc.z : expm1f(acc.z);
    r.w = (acc.w > 0.f) ? acc.w : expm1f(acc.w);
    reinterpret_cast<float4*>(out + (size_t)i * OUT_DIM)[f] = r;
}

// ---------------------------------------------------------------------------
// Launch: fork {conv_w, topk} onto a side stream; join before gemm and
// aggregate. Score fused into the gemm.
// ---------------------------------------------------------------------------
extern "C" void kernel_launch(void* const* d_in, const int* in_sizes, int n_in,
                              void* d_out, int out_size) {
    const float* x   = (const float*)d_in[0];
    const float* adj = (const float*)d_in[1];
    const float* W   = (const float*)d_in[2];
    const float* a   = (const float*)d_in[3];
    float* out = (float*)d_out;

    static cudaStream_t s2 = nullptr;
    static cudaEvent_t ev_fork = nullptr, ev_w = nullptr, ev_topk = nullptr;
    if (s2 == nullptr) {
        cudaStreamCreateWithFlags(&s2, cudaStreamNonBlocking);
        cudaEventCreateWithFlags(&ev_fork, cudaEventDisableTiming);
        cudaEventCreateWithFlags(&ev_w,    cudaEventDisableTiming);
        cudaEventCreateWithFlags(&ev_topk, cudaEventDisableTiming);
        cudaFuncSetAttribute(hmma_gemm_kernel,
                             cudaFuncAttributeMaxDynamicSharedMemorySize, SMEM_DYN);
    }

    cudaEventRecord(ev_fork, 0);
    cudaStreamWaitEvent(s2, ev_fork, 0);

    conv_w_kernel<<<512, 256, 0, s2>>>(W);
    cudaEventRecord(ev_w, s2);
    topk_kernel<<<N_NODES / 4, 128, 0, s2>>>(adj);
    cudaEventRecord(ev_topk, s2);

    conv_x_kernel<<<4096, 256>>>(x);
    cudaStreamWaitEvent(0, ev_w, 0);
    hmma_gemm_kernel<<<dim3(OUT_DIM / 128, N_NODES / 128), 512, SMEM_DYN>>>(a);
    cudaStreamWaitEvent(0, ev_topk, 0);
    aggregate_kernel<<<N_NODES, 128>>>(out);
}